// round 8
// baseline (speedup 1.0000x reference)
#include <cuda_runtime.h>
#include <cstdint>

#define NN 50000
#define NE 800000
#define NG 256
#define NTILE 6250          // NE / 128
#define PGRID 152

typedef unsigned long long ull;

// PHI: involutive permutation within 32-blocks (fragment<->original col map)
__host__ __device__ __forceinline__ int PHI32(int v) {
    return (v & ~31) | (((v >> 1) & 3) << 3) | (((v >> 3) & 3) << 1) | (v & 1);
}

// ---------------- tf32 mma.sync helpers ----------------
__device__ __forceinline__ uint32_t f2tf(float f) {
    uint32_t r; asm("cvt.rna.tf32.f32 %0, %1;" : "=r"(r) : "f"(f)); return r;
}
__device__ __forceinline__ void mma8(float* d, const uint32_t* a, uint32_t b0, uint32_t b1) {
    asm volatile("mma.sync.aligned.m16n8k8.row.col.f32.tf32.tf32.f32 "
        "{%0,%1,%2,%3},{%4,%5,%6,%7},{%8,%9},{%0,%1,%2,%3};"
        : "+f"(d[0]), "+f"(d[1]), "+f"(d[2]), "+f"(d[3])
        : "r"(a[0]), "r"(a[1]), "r"(a[2]), "r"(a[3]), "r"(b0), "r"(b1));
}

// ---------------- f32x2 helpers ----------------
__device__ __forceinline__ void ffma2(ull &d, ull a, ull b) {
    asm("fma.rn.f32x2 %0, %1, %2, %0;" : "+l"(d) : "l"(a), "l"(b));
}
__device__ __forceinline__ ull pack2(float lo, float hi) {
    ull r; asm("mov.b64 %0, {%1, %2};" : "=l"(r) : "f"(lo), "f"(hi)); return r;
}
__device__ __forceinline__ float2 unpack2(ull v) {
    float2 r; asm("mov.b64 {%0, %1}, %2;" : "=f"(r.x), "=f"(r.y) : "l"(v)); return r;
}
__device__ __forceinline__ ull relu2(ull v) {
    float2 t = unpack2(v);
    return pack2(fmaxf(t.x, 0.f), fmaxf(t.y, 0.f));
}
__device__ __forceinline__ void red_add_v4f(float* p, float a, float b, float c, float d) {
    asm volatile("red.global.add.v4.f32 [%0], {%1,%2,%3,%4};" :: "l"(p), "f"(a), "f"(b), "f"(c), "f"(d) : "memory");
}
__device__ __forceinline__ void red_add_f(float* p, float a) {
    asm volatile("red.global.add.f32 [%0], %1;" :: "l"(p), "f"(a) : "memory");
}

// ---------------- device scratch ----------------
__device__ float d_P [NN*128];   // P + Rg[batch[n]] + eb1  (PR-fused)
__device__ float d_Q [NN*128];
__device__ float d_Ms[NN*128];
__device__ float d_Rg[NG*128];
__device__ float d_agg[NN*128];  // PHI-permuted column layout
__device__ float d_deg[NN];
__device__ float d_gsum[NG*64];
__device__ float d_gcnt[NG];

// ---------------- K0 / K0b ----------------
__global__ void k_zero() {
    int i = blockIdx.x * blockDim.x + threadIdx.x;
    int stride = gridDim.x * blockDim.x;
    for (int idx = i; idx < NN*128; idx += stride) d_agg[idx] = 0.f;
    for (int idx = i; idx < NN;     idx += stride) d_deg[idx] = 0.f;
    for (int idx = i; idx < NG*64;  idx += stride) d_gsum[idx] = 0.f;
    for (int idx = i; idx < NG;     idx += stride) d_gcnt[idx] = 0.f;
}
__global__ void k_count(const int* __restrict__ ei, const int* __restrict__ batch) {
    int i = blockIdx.x * blockDim.x + threadIdx.x;
    if (i < NE) atomicAdd(&d_deg[ei[NE + i]], 1.f);
    if (i < NN) atomicAdd(&d_gcnt[batch[i]], 1.f);
}

// ---------------- K1b: R = u @ e_w1[160:176]  (runs BEFORE k_pre) ----------------
__global__ void k_rg(const float* __restrict__ u, const float* __restrict__ ew1) {
    int i = blockIdx.x * blockDim.x + threadIdx.x;
    if (i < NG*128) {
        int g = i >> 7, j = i & 127;
        float acc = 0.f;
        #pragma unroll
        for (int k = 0; k < 16; k++) acc += u[g*16 + k] * ew1[(160 + k)*128 + j];
        d_Rg[i] = acc;
    }
}

// ---------------- K1: precompute PR, Q, Msrc (SIMT f32x2, fp32-exact) ----------------
#define PRE_SMEM ((4352 + 3*8192 + 256 + 64) * 4)
__global__ void __launch_bounds__(512, 1)
k_pre(const float* __restrict__ x, const float* __restrict__ ew1,
      const float* __restrict__ eb1, const float* __restrict__ n1w1,
      const float* __restrict__ n1b1, const int* __restrict__ batch) {
    extern __shared__ float sm[];
    float* sXT  = sm;
    float* sWa  = sm + 4352;
    float* sWb  = sWa + 8192;
    float* sWm  = sWb + 8192;
    float* sEb1 = sWm + 8192;
    float* sNb1 = sEb1 + 128;
    int*   sBat = (int*)(sNb1 + 128);
    int tid = threadIdx.x;
    for (int i = tid; i < 8192; i += 512) {
        sWa[i] = ew1[i];
        sWb[i] = ew1[64*128 + i];
        sWm[i] = n1w1[i];
    }
    if (tid < 128) { sEb1[tid] = eb1[tid]; sNb1[tid] = n1b1[tid]; }
    int n0 = blockIdx.x * 64;
    if (tid < 64) {
        int n = n0 + tid;
        sBat[tid] = (n < NN) ? batch[n] : 0;
    }
    for (int idx = tid; idx < 64*64; idx += 512) {
        int node = idx >> 6, k = idx & 63;
        int n = n0 + node;
        sXT[k*68 + node] = (n < NN) ? x[(size_t)n*64 + k] : 0.f;
    }
    __syncthreads();
    int tx = tid & 31, wid = tid >> 5;
    int ty = wid & 7, fh = wid >> 3;
    int fbase = fh*64 + tx*2;
    for (int which = 0; which < 3; which++) {
        const float* W = (which == 0) ? sWa : (which == 1) ? sWb : sWm;
        ull acc[4][2];
        #pragma unroll
        for (int p = 0; p < 4; p++)
            #pragma unroll
            for (int j = 0; j < 2; j++) {
                float b = (which == 0) ? sEb1[fbase + j] : (which == 2) ? sNb1[fbase + j] : 0.f;
                acc[p][j] = pack2(b, b);
            }
        #pragma unroll 4
        for (int k = 0; k < 64; k++) {
            float2 B = *(const float2*)&W[k*128 + fbase];
            ull bb0 = pack2(B.x, B.x), bb1 = pack2(B.y, B.y);
            float4 A0 = *(const float4*)&sXT[k*68 + ty*8];
            float4 A1 = *(const float4*)&sXT[k*68 + ty*8 + 4];
            ull a0 = pack2(A0.x, A0.y), a1 = pack2(A0.z, A0.w);
            ull a2 = pack2(A1.x, A1.y), a3 = pack2(A1.z, A1.w);
            ffma2(acc[0][0], a0, bb0); ffma2(acc[0][1], a0, bb1);
            ffma2(acc[1][0], a1, bb0); ffma2(acc[1][1], a1, bb1);
            ffma2(acc[2][0], a2, bb0); ffma2(acc[2][1], a2, bb1);
            ffma2(acc[3][0], a3, bb0); ffma2(acc[3][1], a3, bb1);
        }
        float* dst = (which == 0) ? d_P : (which == 1) ? d_Q : d_Ms;
        #pragma unroll
        for (int p = 0; p < 4; p++) {
            float2 v0 = unpack2(acc[p][0]), v1 = unpack2(acc[p][1]);
            int node = ty*8 + 2*p;
            int n_lo = n0 + node;
            if (which == 0) {   // PR-fuse: add Rg[batch[n]]
                if (n_lo < NN) {
                    const float* rg = &d_Rg[(size_t)sBat[node]*128 + fbase];
                    v0.x += rg[0]; v1.x += rg[1];
                }
                if (n_lo + 1 < NN) {
                    const float* rg = &d_Rg[(size_t)sBat[node+1]*128 + fbase];
                    v0.y += rg[0]; v1.y += rg[1];
                }
            }
            if (n_lo < NN)
                *(float2*)&dst[(size_t)n_lo*128 + fbase] = make_float2(v0.x, v1.x);
            if (n_lo + 1 < NN)
                *(float2*)&dst[(size_t)(n_lo+1)*128 + fbase] = make_float2(v0.y, v1.y);
        }
    }
}

// ================= K2a: EdgeModel via tf32 mma.sync — 1024 thr, pi-permuted =================
// words: sW1u 4096 | sW2u 8192 | sH1 128*132 | sB2 64 | idx 256
#define S2A_SMEM ((4096 + 8192 + 16896 + 64 + 256) * 4)
__global__ void __launch_bounds__(1024, 1)
k2a(const float* __restrict__ ea, const float* __restrict__ ew1,
    const float* __restrict__ ew2, const float* __restrict__ eb2,
    const int* __restrict__ ei, float* __restrict__ outE) {
    extern __shared__ float sm[];
    uint32_t* sW1u = (uint32_t*)sm;              // [gnt*4+ks][64] frag order
    uint32_t* sW2u = (uint32_t*)(sm + 4096);     // [gnt*16+ks][64]
    uint32_t* sH1  = (uint32_t*)(sm + 12288);    // [128e][132]  (pi space, frag-natural)
    float*    sB2  = sm + 29184;                 // 64
    int* sRow = (int*)(sm + 29248);
    int* sCol = sRow + 128;

    int tid = threadIdx.x, lane = tid & 31, w = tid >> 5;
    int wm = w & 7, wn = w >> 3;
    int g = lane >> 2, tig = lane & 3;
    int e1 = wm*16 + g, e2 = e1 + 8;

    // ---- weight staging (fragment order, tf32, pi-compensated) ----
    for (int i = tid; i < 4096; i += 1024) {     // W1c^T: n pi-permuted, k natural (EA space)
        int blk = i >> 6, j = i & 63;
        int gnt = blk >> 2, ks = blk & 3;
        int l = j >> 1, h = j & 1;
        int p = l >> 2;
        int k = ks*8 + (l & 3) + h*4;
        int n_orig = (gnt >> 2)*32 + (p >> 1)*8 + (gnt & 3)*2 + (p & 1);
        sW1u[i] = f2tf(ew1[(128 + k)*128 + n_orig]);
    }
    for (int i = tid; i < 8192; i += 1024) {     // W2^T: k pi (H1 space), n pi16 (outE vec)
        int blk = i >> 6, j = i & 63;
        int gnt = blk >> 4, ks = blk & 15;
        int l = j >> 1, h = j & 1;
        int p = l >> 2;
        int v = ks*8 + (l & 3) + h*4;
        int k_orig = PHI32(v);
        int n_orig = (gnt >> 1)*16 + (p >> 1)*4 + (gnt & 1)*2 + (p & 1);
        sW2u[i] = f2tf(ew2[k_orig*64 + n_orig]);
    }
    if (tid < 64) sB2[tid] = eb2[tid];

    for (int t = blockIdx.x; t < NTILE; t += gridDim.x) {
        __syncthreads();
        int e0 = t * 128;
        if (tid < 128) {
            sRow[tid] = ei[e0 + tid];
            sCol[tid] = ei[NE + e0 + tid];
        }
        __syncthreads();

        int r1 = sRow[e1], cc1 = sCol[e1];
        int r2 = sRow[e2], cc2 = sCol[e2];

        // ---- GEMM1 seeds: PR[row] + Q[col], contiguous float4 pairs ----
        float acc[4][4];
        {
            const float4* P1 = (const float4*)&d_P[(size_t)r1*128 + wn*32 + tig*8];
            const float4* Q1 = (const float4*)&d_Q[(size_t)cc1*128 + wn*32 + tig*8];
            const float4* P2 = (const float4*)&d_P[(size_t)r2*128 + wn*32 + tig*8];
            const float4* Q2 = (const float4*)&d_Q[(size_t)cc2*128 + wn*32 + tig*8];
            float4 a0 = P1[0], b0 = Q1[0], a1 = P1[1], b1 = Q1[1];
            float4 c0 = P2[0], d0 = Q2[0], c1 = P2[1], d1 = Q2[1];
            acc[0][0] = a0.x + b0.x; acc[0][1] = a0.y + b0.y;
            acc[1][0] = a0.z + b0.z; acc[1][1] = a0.w + b0.w;
            acc[2][0] = a1.x + b1.x; acc[2][1] = a1.y + b1.y;
            acc[3][0] = a1.z + b1.z; acc[3][1] = a1.w + b1.w;
            acc[0][2] = c0.x + d0.x; acc[0][3] = c0.y + d0.y;
            acc[1][2] = c0.z + d0.z; acc[1][3] = c0.w + d0.w;
            acc[2][2] = c1.x + d1.x; acc[2][3] = c1.y + d1.y;
            acc[3][2] = c1.z + d1.z; acc[3][3] = c1.w + d1.w;
        }
        // ---- GEMM1: += EA @ W1c  (K=32, A direct from gmem) ----
        const float* ear1 = &ea[(size_t)(e0 + e1)*32 + tig];
        const float* ear2 = &ea[(size_t)(e0 + e2)*32 + tig];
        #pragma unroll
        for (int ks = 0; ks < 4; ks++) {
            uint32_t a[4];
            a[0] = f2tf(ear1[ks*8]);
            a[1] = f2tf(ear2[ks*8]);
            a[2] = f2tf(ear1[ks*8 + 4]);
            a[3] = f2tf(ear2[ks*8 + 4]);
            #pragma unroll
            for (int nt = 0; nt < 4; nt++) {
                const uint32_t* bp = &sW1u[((wn*4 + nt)*4 + ks)*64 + lane*2];
                mma8(acc[nt], a, bp[0], bp[1]);
            }
        }
        // ---- store H1' (pi space, fragment-natural cols) ----
        #pragma unroll
        for (int nt = 0; nt < 4; nt++) {
            int c = wn*32 + nt*8 + tig*2;
            *(uint2*)&sH1[e1*132 + c] =
                make_uint2(f2tf(fmaxf(acc[nt][0], 0.f)), f2tf(fmaxf(acc[nt][1], 0.f)));
            *(uint2*)&sH1[e2*132 + c] =
                make_uint2(f2tf(fmaxf(acc[nt][2], 0.f)), f2tf(fmaxf(acc[nt][3], 0.f)));
        }
        __syncthreads();

        // ---- GEMM2: EN = H1 @ W2 + b2  (K=128, N=64) → outE (vectorized) ----
        float acc2[2][4];
        {
            float4 b = *(const float4*)&sB2[wn*16 + tig*4];
            acc2[0][0] = b.x; acc2[0][1] = b.y; acc2[1][0] = b.z; acc2[1][1] = b.w;
            acc2[0][2] = b.x; acc2[0][3] = b.y; acc2[1][2] = b.z; acc2[1][3] = b.w;
        }
        #pragma unroll 4
        for (int ks = 0; ks < 16; ks++) {
            uint32_t a[4];
            a[0] = sH1[e1*132 + ks*8 + tig];
            a[1] = sH1[e2*132 + ks*8 + tig];
            a[2] = sH1[e1*132 + ks*8 + tig + 4];
            a[3] = sH1[e2*132 + ks*8 + tig + 4];
            #pragma unroll
            for (int nt = 0; nt < 2; nt++) {
                const uint32_t* bp = &sW2u[((wn*2 + nt)*16 + ks)*64 + lane*2];
                mma8(acc2[nt], a, bp[0], bp[1]);
            }
        }
        *(float4*)&outE[(size_t)(e0 + e1)*64 + wn*16 + tig*4] =
            make_float4(acc2[0][0], acc2[0][1], acc2[1][0], acc2[1][1]);
        *(float4*)&outE[(size_t)(e0 + e2)*64 + wn*16 + tig*4] =
            make_float4(acc2[0][2], acc2[0][3], acc2[1][2], acc2[1][3]);
    }
}

// ================= K2b: message MLP via tf32 mma.sync — 1024 thr, pi-permuted =================
// words: sW3u 8192 | sW4u 16384 | sH2 128*132 | sB4 128 | idx 256
#define S2B_SMEM ((8192 + 16384 + 16896 + 128 + 256) * 4)
__global__ void __launch_bounds__(1024, 1)
k2b(const float* __restrict__ n1w1, const float* __restrict__ n1w2,
    const float* __restrict__ n1b2,
    const int* __restrict__ ei, const float* __restrict__ edgeNew) {
    extern __shared__ float sm[];
    uint32_t* sW3u = (uint32_t*)sm;              // [gnt*8+ks][64]
    uint32_t* sW4u = (uint32_t*)(sm + 8192);     // [gnt*16+ks][64]
    uint32_t* sH2  = (uint32_t*)(sm + 24576);    // [128e][132] (pi space)
    float*    sB4  = sm + 41472;                 // 128
    int* sRow = (int*)(sm + 41600);
    int* sCol = sRow + 128;

    int tid = threadIdx.x, lane = tid & 31, w = tid >> 5;
    int wm = w & 7, wn = w >> 3;
    int g = lane >> 2, tig = lane & 3;
    int e1 = wm*16 + g, e2 = e1 + 8;

    for (int i = tid; i < 8192; i += 1024) {     // W3^T: n pi-permuted, k natural (EN space)
        int blk = i >> 6, j = i & 63;
        int gnt = blk >> 3, ks = blk & 7;
        int l = j >> 1, h = j & 1;
        int p = l >> 2;
        int k = ks*8 + (l & 3) + h*4;
        int n_orig = (gnt >> 2)*32 + (p >> 1)*8 + (gnt & 3)*2 + (p & 1);
        sW3u[i] = f2tf(n1w1[(64 + k)*128 + n_orig]);
    }
    for (int i = tid; i < 16384; i += 1024) {    // W4^T: k pi (H2 space), n natural
        int blk = i >> 6, j = i & 63;
        int gnt = blk >> 4, ks = blk & 15;
        int l = j >> 1, h = j & 1;
        int p = l >> 2;
        int v = ks*8 + (l & 3) + h*4;
        int k_orig = PHI32(v);
        int n = gnt*8 + p;
        sW4u[i] = f2tf(n1w2[k_orig*128 + n]);
    }
    if (tid < 128) sB4[tid] = n1b2[tid];

    for (int t = blockIdx.x; t < NTILE; t += gridDim.x) {
        __syncthreads();
        int e0 = t * 128;
        if (tid < 128) {
            sRow[tid] = ei[e0 + tid];
            sCol[tid] = ei[NE + e0 + tid];
        }
        __syncthreads();

        int r1 = sRow[e1], r2 = sRow[e2];
        int c1 = sCol[e1], c2 = sCol[e2];

        // ---- GEMM3 seeds: Ms[row], contiguous float4 pairs ----
        float acc[4][4];
        {
            const float4* M1 = (const float4*)&d_Ms[(size_t)r1*128 + wn*32 + tig*8];
            const float4* M2 = (const float4*)&d_Ms[(size_t)r2*128 + wn*32 + tig*8];
            float4 a0 = M1[0], a1 = M1[1], b0 = M2[0], b1 = M2[1];
            acc[0][0] = a0.x; acc[0][1] = a0.y; acc[1][0] = a0.z; acc[1][1] = a0.w;
            acc[2][0] = a1.x; acc[2][1] = a1.y; acc[3][0] = a1.z; acc[3][1] = a1.w;
            acc[0][2] = b0.x; acc[0][3] = b0.y; acc[1][2] = b0.z; acc[1][3] = b0.w;
            acc[2][2] = b1.x; acc[2][3] = b1.y; acc[3][2] = b1.z; acc[3][3] = b1.w;
        }
        // ---- GEMM3: += EN @ W3  (K=64, A direct from gmem) ----
        const float* en1 = &edgeNew[(size_t)(e0 + e1)*64 + tig];
        const float* en2 = &edgeNew[(size_t)(e0 + e2)*64 + tig];
        #pragma unroll
        for (int ks = 0; ks < 8; ks++) {
            uint32_t a[4];
            a[0] = f2tf(en1[ks*8]);
            a[1] = f2tf(en2[ks*8]);
            a[2] = f2tf(en1[ks*8 + 4]);
            a[3] = f2tf(en2[ks*8 + 4]);
            #pragma unroll
            for (int nt = 0; nt < 4; nt++) {
                const uint32_t* bp = &sW3u[((wn*4 + nt)*8 + ks)*64 + lane*2];
                mma8(acc[nt], a, bp[0], bp[1]);
            }
        }
        #pragma unroll
        for (int nt = 0; nt < 4; nt++) {
            int c = wn*32 + nt*8 + tig*2;
            *(uint2*)&sH2[e1*132 + c] =
                make_uint2(f2tf(fmaxf(acc[nt][0], 0.f)), f2tf(fmaxf(acc[nt][1], 0.f)));
            *(uint2*)&sH2[e2*132 + c] =
                make_uint2(f2tf(fmaxf(acc[nt][2], 0.f)), f2tf(fmaxf(acc[nt][3], 0.f)));
        }
        __syncthreads();

        // ---- GEMM4: m = H2 @ W4 + b4  (K=128, N=128) → v4 scatter (agg pi space) ----
        float acc4[4][4];
        #pragma unroll
        for (int nt = 0; nt < 4; nt++) {
            int c = wn*32 + nt*8 + tig*2;     // original feature cols (n natural)
            acc4[nt][0] = sB4[c]; acc4[nt][1] = sB4[c+1];
            acc4[nt][2] = sB4[c]; acc4[nt][3] = sB4[c+1];
        }
        #pragma unroll 4
        for (int ks = 0; ks < 16; ks++) {
            uint32_t a[4];
            a[0] = sH2[e1*132 + ks*8 + tig];
            a[1] = sH2[e2*132 + ks*8 + tig];
            a[2] = sH2[e1*132 + ks*8 + tig + 4];
            a[3] = sH2[e2*132 + ks*8 + tig + 4];
            #pragma unroll
            for (int nt = 0; nt < 4; nt++) {
                const uint32_t* bp = &sW4u[((wn*4 + nt)*16 + ks)*64 + lane*2];
                mma8(acc4[nt], a, bp[0], bp[1]);
            }
        }
        // agg stored pi-permuted: feature (wn*32+nt*8+2tig+b) lives at col (wn*32+tig*8+nt*2+b)
        {
            float* b1p = &d_agg[(size_t)c1*128 + wn*32 + tig*8];
            red_add_v4f(b1p,     acc4[0][0], acc4[0][1], acc4[1][0], acc4[1][1]);
            red_add_v4f(b1p + 4, acc4[2][0], acc4[2][1], acc4[3][0], acc4[3][1]);
            float* b2p = &d_agg[(size_t)c2*128 + wn*32 + tig*8];
            red_add_v4f(b2p,     acc4[0][2], acc4[0][3], acc4[1][2], acc4[1][3]);
            red_add_v4f(b2p + 4, acc4[2][2], acc4[2][3], acc4[3][2], acc4[3][3]);
        }
    }
}

// ---------------- K3: node MLP2 + pooling (SIMT f32x2; un-permutes agg) ----------------
#define NODE_SMEM (49280 * 4)
__global__ void __launch_bounds__(512, 1)
k_node(const float* __restrict__ x, const float* __restrict__ u,
       const float* __restrict__ n2w1, const float* __restrict__ n2b1,
       const float* __restrict__ n2w2, const float* __restrict__ n2b2,
       const int* __restrict__ batch, float* __restrict__ outX) {
    extern __shared__ float sm[];
    float* sW1  = sm;
    float* sW2  = sm + 26624;
    float* sB1  = sm + 34816;
    float* sB2  = sm + 34944;
    float* sInT = sm + 35008;
    float* sInv = sm + 49152;
    int*   sBat = (int*)(sm + 49216);

    int tid = threadIdx.x, tx = tid & 31, wid = tid >> 5;
    int ty = wid & 7, fh = wid >> 3;
    int fbase = fh*64 + tx*2;
    int f2 = fh*32 + tx;

    for (int i = tid; i < 26624; i += 512) sW1[i] = n2w1[i];
    for (int i = tid; i < 8192;  i += 512) sW2[i] = n2w2[i];
    if (tid < 128) sB1[tid] = n2b1[tid];
    if (tid < 64)  sB2[tid] = n2b2[tid];

    int n0 = blockIdx.x * 64;
    if (tid < 64) {
        int n = n0 + tid;
        if (n < NN) { sBat[tid] = batch[n]; sInv[tid] = 1.f / fmaxf(d_deg[n], 1.f); }
        else        { sBat[tid] = 0;        sInv[tid] = 0.f; }
    }
    __syncthreads();
    for (int idx = tid; idx < 64*64; idx += 512) {
        int node = idx >> 6, k = idx & 63; int n = n0 + node;
        sInT[k*68 + node] = (n < NN) ? x[(size_t)n*64 + k] : 0.f;
    }
    for (int idx = tid; idx < 64*128; idx += 512) {
        int node = idx >> 7, k = idx & 127; int n = n0 + node;
        sInT[(64 + k)*68 + node] = (n < NN) ? d_agg[(size_t)n*128 + PHI32(k)] * sInv[node] : 0.f;
    }
    for (int idx = tid; idx < 64*16; idx += 512) {
        int node = idx >> 4, k = idx & 15;
        sInT[(192 + k)*68 + node] = u[sBat[node]*16 + k];
    }
    __syncthreads();

    ull acc[4][2];
    #pragma unroll
    for (int p = 0; p < 4; p++) {
        acc[p][0] = pack2(sB1[fbase],     sB1[fbase]);
        acc[p][1] = pack2(sB1[fbase + 1], sB1[fbase + 1]);
    }
    #pragma unroll 4
    for (int k = 0; k < 208; k++) {
        float2 B = *(const float2*)&sW1[k*128 + fbase];
        ull bb0 = pack2(B.x, B.x), bb1 = pack2(B.y, B.y);
        float4 A0 = *(const float4*)&sInT[k*68 + ty*8];
        float4 A1 = *(const float4*)&sInT[k*68 + ty*8 + 4];
        ull a0 = pack2(A0.x, A0.y), a1 = pack2(A0.z, A0.w);
        ull a2 = pack2(A1.x, A1.y), a3 = pack2(A1.z, A1.w);
        ffma2(acc[0][0], a0, bb0); ffma2(acc[0][1], a0, bb1);
        ffma2(acc[1][0], a1, bb0); ffma2(acc[1][1], a1, bb1);
        ffma2(acc[2][0], a2, bb0); ffma2(acc[2][1], a2, bb1);
        ffma2(acc[3][0], a3, bb0); ffma2(acc[3][1], a3, bb1);
    }
    __syncthreads();
    #pragma unroll
    for (int p = 0; p < 4; p++) {
        *(ull*)&sInT[(fbase + 0)*68 + ty*8 + 2*p] = relu2(acc[p][0]);
        *(ull*)&sInT[(fbase + 1)*68 + ty*8 + 2*p] = relu2(acc[p][1]);
    }
    __syncthreads();

    ull acc2[4];
    {
        float b = sB2[f2];
        #pragma unroll
        for (int p = 0; p < 4; p++) acc2[p] = pack2(b, b);
    }
    #pragma unroll 4
    for (int k = 0; k < 128; k++) {
        float bs = sW2[k*64 + f2];
        ull bb = pack2(bs, bs);
        float4 A0 = *(const float4*)&sInT[k*68 + ty*8];
        float4 A1 = *(const float4*)&sInT[k*68 + ty*8 + 4];
        ffma2(acc2[0], pack2(A0.x, A0.y), bb);
        ffma2(acc2[1], pack2(A0.z, A0.w), bb);
        ffma2(acc2[2], pack2(A1.x, A1.y), bb);
        ffma2(acc2[3], pack2(A1.z, A1.w), bb);
    }
    #pragma unroll
    for (int p = 0; p < 4; p++) {
        float2 v = unpack2(acc2[p]);
        int node = ty*8 + 2*p;
        int n_lo = n0 + node;
        if (n_lo < NN) {
            outX[(size_t)n_lo*64 + f2] = v.x;
            red_add_f(&d_gsum[sBat[node]*64 + f2], v.x);
        }
        if (n_lo + 1 < NN) {
            outX[(size_t)(n_lo+1)*64 + f2] = v.y;
            red_add_f(&d_gsum[sBat[node+1]*64 + f2], v.y);
        }
    }
}

// ---------------- K4: global MLP ----------------
__global__ void k_glob(const float* __restrict__ u,
                       const float* __restrict__ gw1, const float* __restrict__ gb1,
                       const float* __restrict__ gw2, const float* __restrict__ gb2,
                       float* __restrict__ outU) {
    __shared__ float sin[80];
    __shared__ float sh[128];
    int g = blockIdx.x, tid = threadIdx.x;
    if (tid < 16) sin[tid] = u[g*16 + tid];
    if (tid < 64) {
        float c = fmaxf(d_gcnt[g], 1.f);
        sin[16 + tid] = d_gsum[g*64 + tid] / c;
    }
    __syncthreads();
    float acc = gb1[tid];
    #pragma unroll 8
    for (int k = 0; k < 80; k++) acc += sin[k] * gw1[k*128 + tid];
    sh[tid] = fmaxf(acc, 0.f);
    __syncthreads();
    if (tid < 32) {
        float a2 = gb2[tid];
        #pragma unroll 8
        for (int k = 0; k < 128; k++) a2 += sh[k] * gw2[k*32 + tid];
        outU[g*32 + tid] = a2;
    }
}

// ---------------- launch ----------------
extern "C" void kernel_launch(void* const* d_in, const int* in_sizes, int n_in,
                              void* d_out, int out_size) {
    const float* x     = (const float*)d_in[0];
    const float* ea    = (const float*)d_in[1];
    const float* u     = (const float*)d_in[2];
    const float* ew1   = (const float*)d_in[3];
    const float* eb1   = (const float*)d_in[4];
    const float* ew2   = (const float*)d_in[5];
    const float* eb2   = (const float*)d_in[6];
    const float* n1w1  = (const float*)d_in[7];
    const float* n1b1  = (const float*)d_in[8];
    const float* n1w2  = (const float*)d_in[9];
    const float* n1b2  = (const float*)d_in[10];
    const float* n2w1  = (const float*)d_in[11];
    const float* n2b1  = (const float*)d_in[12];
    const float* n2w2  = (const float*)d_in[13];
    const float* n2b2  = (const float*)d_in[14];
    const float* gw1   = (const float*)d_in[15];
    const float* gb1   = (const float*)d_in[16];
    const float* gw2   = (const float*)d_in[17];
    const float* gb2   = (const float*)d_in[18];
    const int*   ei    = (const int*)d_in[19];
    const int*   batch = (const int*)d_in[20];

    float* out  = (float*)d_out;
    float* outX = out;
    float* outE = out + (size_t)NN*64;
    float* outU = out + (size_t)NN*64 + (size_t)NE*64;

    cudaFuncSetAttribute(k_pre,  cudaFuncAttributeMaxDynamicSharedMemorySize, PRE_SMEM);
    cudaFuncSetAttribute(k2a,    cudaFuncAttributeMaxDynamicSharedMemorySize, S2A_SMEM);
    cudaFuncSetAttribute(k2b,    cudaFuncAttributeMaxDynamicSharedMemorySize, S2B_SMEM);
    cudaFuncSetAttribute(k_node, cudaFuncAttributeMaxDynamicSharedMemorySize, NODE_SMEM);

    k_zero<<<256, 256>>>();
    k_rg<<<(NG*128 + 255)/256, 256>>>(u, ew1);
    k_pre<<<(NN + 63)/64, 512, PRE_SMEM>>>(x, ew1, eb1, n1w1, n1b1, batch);
    k2a<<<PGRID, 1024, S2A_SMEM>>>(ea, ew1, ew2, eb2, ei, outE);
    k2b<<<PGRID, 1024, S2B_SMEM>>>(n1w1, n1w2, n1b2, ei, outE);
    k_count<<<(NE + 255)/256, 256>>>(ei, batch);
    k_node<<<(NN + 63)/64, 512, NODE_SMEM>>>(x, u, n2w1, n2b1, n2w2, n2b2, batch, outX);
    k_glob<<<NG, 128>>>(u, gw1, gb1, gw2, gb2, outU);
}

// round 9
// speedup vs baseline: 1.0698x; 1.0698x over previous
#include <cuda_runtime.h>
#include <cstdint>

#define NN 50000
#define NE 800000
#define NG 256
#define NTILE 6250          // NE / 128
#define PGRID 152

typedef unsigned long long ull;

// PHI: involutive permutation within 32-blocks (fragment<->original col map)
__host__ __device__ __forceinline__ int PHI32(int v) {
    return (v & ~31) | (((v >> 1) & 3) << 3) | (((v >> 3) & 3) << 1) | (v & 1);
}

// ---------------- tf32 mma.sync helpers ----------------
__device__ __forceinline__ uint32_t f2tf(float f) {
    uint32_t r; asm("cvt.rna.tf32.f32 %0, %1;" : "=r"(r) : "f"(f)); return r;
}
__device__ __forceinline__ void mma8(float* d, const uint32_t* a, uint32_t b0, uint32_t b1) {
    asm volatile("mma.sync.aligned.m16n8k8.row.col.f32.tf32.tf32.f32 "
        "{%0,%1,%2,%3},{%4,%5,%6,%7},{%8,%9},{%0,%1,%2,%3};"
        : "+f"(d[0]), "+f"(d[1]), "+f"(d[2]), "+f"(d[3])
        : "r"(a[0]), "r"(a[1]), "r"(a[2]), "r"(a[3]), "r"(b0), "r"(b1));
}

// ---------------- f32x2 helpers ----------------
__device__ __forceinline__ void ffma2(ull &d, ull a, ull b) {
    asm("fma.rn.f32x2 %0, %1, %2, %0;" : "+l"(d) : "l"(a), "l"(b));
}
__device__ __forceinline__ ull pack2(float lo, float hi) {
    ull r; asm("mov.b64 %0, {%1, %2};" : "=l"(r) : "f"(lo), "f"(hi)); return r;
}
__device__ __forceinline__ float2 unpack2(ull v) {
    float2 r; asm("mov.b64 {%0, %1}, %2;" : "=f"(r.x), "=f"(r.y) : "l"(v)); return r;
}
__device__ __forceinline__ ull relu2(ull v) {
    float2 t = unpack2(v);
    return pack2(fmaxf(t.x, 0.f), fmaxf(t.y, 0.f));
}
__device__ __forceinline__ void red_add_v4f(float* p, float a, float b, float c, float d) {
    asm volatile("red.global.add.v4.f32 [%0], {%1,%2,%3,%4};" :: "l"(p), "f"(a), "f"(b), "f"(c), "f"(d) : "memory");
}
__device__ __forceinline__ void red_add_f(float* p, float a) {
    asm volatile("red.global.add.f32 [%0], %1;" :: "l"(p), "f"(a) : "memory");
}

// ---------------- device scratch ----------------
__device__ float d_P [NN*128];   // P + Rg[batch[n]] + eb1  (PR-fused)
__device__ float d_Q [NN*128];
__device__ float d_Ms[NN*128];
__device__ float d_Rg[NG*128];
__device__ float d_agg[NN*128];  // PHI-permuted column layout
__device__ float d_deg[NN];
__device__ float d_gsum[NG*64];
__device__ float d_gcnt[NG];

// ---------------- K0 / K0b ----------------
__global__ void k_zero() {
    int i = blockIdx.x * blockDim.x + threadIdx.x;
    int stride = gridDim.x * blockDim.x;
    for (int idx = i; idx < NN*128; idx += stride) d_agg[idx] = 0.f;
    for (int idx = i; idx < NN;     idx += stride) d_deg[idx] = 0.f;
    for (int idx = i; idx < NG*64;  idx += stride) d_gsum[idx] = 0.f;
    for (int idx = i; idx < NG;     idx += stride) d_gcnt[idx] = 0.f;
}
__global__ void k_count(const int* __restrict__ ei, const int* __restrict__ batch) {
    int i = blockIdx.x * blockDim.x + threadIdx.x;
    if (i < NE) atomicAdd(&d_deg[ei[NE + i]], 1.f);
    if (i < NN) atomicAdd(&d_gcnt[batch[i]], 1.f);
}

// ---------------- K1b: R = u @ e_w1[160:176]  (runs BEFORE k_pre) ----------------
__global__ void k_rg(const float* __restrict__ u, const float* __restrict__ ew1) {
    int i = blockIdx.x * blockDim.x + threadIdx.x;
    if (i < NG*128) {
        int g = i >> 7, j = i & 127;
        float acc = 0.f;
        #pragma unroll
        for (int k = 0; k < 16; k++) acc += u[g*16 + k] * ew1[(160 + k)*128 + j];
        d_Rg[i] = acc;
    }
}

// ---------------- K1: precompute PR, Q, Msrc (SIMT f32x2, fp32-exact) ----------------
#define PRE_SMEM ((4352 + 3*8192 + 256 + 64) * 4)
__global__ void __launch_bounds__(512, 1)
k_pre(const float* __restrict__ x, const float* __restrict__ ew1,
      const float* __restrict__ eb1, const float* __restrict__ n1w1,
      const float* __restrict__ n1b1, const int* __restrict__ batch) {
    extern __shared__ float sm[];
    float* sXT  = sm;
    float* sWa  = sm + 4352;
    float* sWb  = sWa + 8192;
    float* sWm  = sWb + 8192;
    float* sEb1 = sWm + 8192;
    float* sNb1 = sEb1 + 128;
    int*   sBat = (int*)(sNb1 + 128);
    int tid = threadIdx.x;
    for (int i = tid; i < 8192; i += 512) {
        sWa[i] = ew1[i];
        sWb[i] = ew1[64*128 + i];
        sWm[i] = n1w1[i];
    }
    if (tid < 128) { sEb1[tid] = eb1[tid]; sNb1[tid] = n1b1[tid]; }
    int n0 = blockIdx.x * 64;
    if (tid < 64) {
        int n = n0 + tid;
        sBat[tid] = (n < NN) ? batch[n] : 0;
    }
    for (int idx = tid; idx < 64*64; idx += 512) {
        int node = idx >> 6, k = idx & 63;
        int n = n0 + node;
        sXT[k*68 + node] = (n < NN) ? x[(size_t)n*64 + k] : 0.f;
    }
    __syncthreads();
    int tx = tid & 31, wid = tid >> 5;
    int ty = wid & 7, fh = wid >> 3;
    int fbase = fh*64 + tx*2;
    for (int which = 0; which < 3; which++) {
        const float* W = (which == 0) ? sWa : (which == 1) ? sWb : sWm;
        ull acc[4][2];
        #pragma unroll
        for (int p = 0; p < 4; p++)
            #pragma unroll
            for (int j = 0; j < 2; j++) {
                float b = (which == 0) ? sEb1[fbase + j] : (which == 2) ? sNb1[fbase + j] : 0.f;
                acc[p][j] = pack2(b, b);
            }
        #pragma unroll 4
        for (int k = 0; k < 64; k++) {
            float2 B = *(const float2*)&W[k*128 + fbase];
            ull bb0 = pack2(B.x, B.x), bb1 = pack2(B.y, B.y);
            float4 A0 = *(const float4*)&sXT[k*68 + ty*8];
            float4 A1 = *(const float4*)&sXT[k*68 + ty*8 + 4];
            ull a0 = pack2(A0.x, A0.y), a1 = pack2(A0.z, A0.w);
            ull a2 = pack2(A1.x, A1.y), a3 = pack2(A1.z, A1.w);
            ffma2(acc[0][0], a0, bb0); ffma2(acc[0][1], a0, bb1);
            ffma2(acc[1][0], a1, bb0); ffma2(acc[1][1], a1, bb1);
            ffma2(acc[2][0], a2, bb0); ffma2(acc[2][1], a2, bb1);
            ffma2(acc[3][0], a3, bb0); ffma2(acc[3][1], a3, bb1);
        }
        float* dst = (which == 0) ? d_P : (which == 1) ? d_Q : d_Ms;
        #pragma unroll
        for (int p = 0; p < 4; p++) {
            float2 v0 = unpack2(acc[p][0]), v1 = unpack2(acc[p][1]);
            int node = ty*8 + 2*p;
            int n_lo = n0 + node;
            if (which == 0) {   // PR-fuse
                if (n_lo < NN) {
                    const float* rg = &d_Rg[(size_t)sBat[node]*128 + fbase];
                    v0.x += rg[0]; v1.x += rg[1];
                }
                if (n_lo + 1 < NN) {
                    const float* rg = &d_Rg[(size_t)sBat[node+1]*128 + fbase];
                    v0.y += rg[0]; v1.y += rg[1];
                }
            }
            if (n_lo < NN)
                *(float2*)&dst[(size_t)n_lo*128 + fbase] = make_float2(v0.x, v1.x);
            if (n_lo + 1 < NN)
                *(float2*)&dst[(size_t)(n_lo+1)*128 + fbase] = make_float2(v0.y, v1.y);
        }
    }
}

// ================= K2a: EdgeModel via tf32 mma.sync — 1024 thr, paired-B LDS.128 =================
// words: sW1p 4096 | sW2p 8192 | sH1 128*132 | sB2 64 | idx 256
#define S2A_SMEM ((4096 + 8192 + 16896 + 64 + 256) * 4)
__global__ void __launch_bounds__(1024, 1)
k2a(const float* __restrict__ ea, const float* __restrict__ ew1,
    const float* __restrict__ ew2, const float* __restrict__ eb2,
    const int* __restrict__ ei, float* __restrict__ outE) {
    extern __shared__ float sm[];
    uint32_t* sW1p = (uint32_t*)sm;              // [((wn*4+ks)*2+pr)][128]
    uint32_t* sW2p = (uint32_t*)(sm + 4096);     // [(wn*16+ks)][128]
    uint32_t* sH1  = (uint32_t*)(sm + 12288);    // [128e][132]
    float*    sB2  = sm + 29184;                 // 64
    int* sRow = (int*)(sm + 29248);
    int* sCol = sRow + 128;

    int tid = threadIdx.x, lane = tid & 31, w = tid >> 5;
    int wm = w & 7, wn = w >> 3;
    int g = lane >> 2, tig = lane & 3;
    int e1 = wm*16 + g, e2 = e1 + 8;

    // ---- W1c^T paired layout: i = ((wn*4+ks)*2+pr)*128 + lane*4 + q ----
    for (int i = tid; i < 4096; i += 1024) {
        int q = i & 3, ln = (i >> 2) & 31, pr = (i >> 7) & 1;
        int ks = (i >> 8) & 3, wn_ = (i >> 10) & 3;
        int nt = pr*2 + (q >> 1), h = q & 1;
        int gnt = wn_*4 + nt, p = ln >> 2;
        int n_orig = (gnt >> 2)*32 + (p >> 1)*8 + (gnt & 3)*2 + (p & 1);
        int k = ks*8 + (ln & 3) + h*4;
        sW1p[i] = f2tf(ew1[(128 + k)*128 + n_orig]);
    }
    // ---- W2^T paired: i = (wn*16+ks)*128 + lane*4 + q ----
    for (int i = tid; i < 8192; i += 1024) {
        int q = i & 3, ln = (i >> 2) & 31;
        int ks = (i >> 7) & 15, wn_ = (i >> 11) & 3;
        int nt = q >> 1, h = q & 1;
        int gnt = wn_*2 + nt, p = ln >> 2;
        int n_orig = (gnt >> 1)*16 + (p >> 1)*4 + (gnt & 1)*2 + (p & 1);
        int k_orig = PHI32(ks*8 + (ln & 3) + h*4);
        sW2p[i] = f2tf(ew2[k_orig*64 + n_orig]);
    }
    if (tid < 64) sB2[tid] = eb2[tid];

    for (int t = blockIdx.x; t < NTILE; t += gridDim.x) {
        __syncthreads();
        int e0 = t * 128;
        if (tid < 128) {
            sRow[tid] = ei[e0 + tid];
            sCol[tid] = ei[NE + e0 + tid];
        }
        __syncthreads();

        int r1 = sRow[e1], cc1 = sCol[e1];
        int r2 = sRow[e2], cc2 = sCol[e2];

        // ---- GEMM1 seeds: PR[row] + Q[col] (contiguous float4 pairs) ----
        float acc[4][4];
        {
            const float4* P1 = (const float4*)&d_P[(size_t)r1*128 + wn*32 + tig*8];
            const float4* Q1 = (const float4*)&d_Q[(size_t)cc1*128 + wn*32 + tig*8];
            const float4* P2 = (const float4*)&d_P[(size_t)r2*128 + wn*32 + tig*8];
            const float4* Q2 = (const float4*)&d_Q[(size_t)cc2*128 + wn*32 + tig*8];
            float4 a0 = P1[0], b0 = Q1[0], a1 = P1[1], b1 = Q1[1];
            float4 c0 = P2[0], d0 = Q2[0], c1 = P2[1], d1 = Q2[1];
            acc[0][0] = a0.x + b0.x; acc[0][1] = a0.y + b0.y;
            acc[1][0] = a0.z + b0.z; acc[1][1] = a0.w + b0.w;
            acc[2][0] = a1.x + b1.x; acc[2][1] = a1.y + b1.y;
            acc[3][0] = a1.z + b1.z; acc[3][1] = a1.w + b1.w;
            acc[0][2] = c0.x + d0.x; acc[0][3] = c0.y + d0.y;
            acc[1][2] = c0.z + d0.z; acc[1][3] = c0.w + d0.w;
            acc[2][2] = c1.x + d1.x; acc[2][3] = c1.y + d1.y;
            acc[3][2] = c1.z + d1.z; acc[3][3] = c1.w + d1.w;
        }
        // ---- GEMM1: += EA @ W1c  (K=32, A direct from gmem) ----
        const float* ear1 = &ea[(size_t)(e0 + e1)*32 + tig];
        const float* ear2 = &ea[(size_t)(e0 + e2)*32 + tig];
        #pragma unroll
        for (int ks = 0; ks < 4; ks++) {
            uint32_t a[4];
            a[0] = f2tf(ear1[ks*8]);
            a[1] = f2tf(ear2[ks*8]);
            a[2] = f2tf(ear1[ks*8 + 4]);
            a[3] = f2tf(ear2[ks*8 + 4]);
            uint4 b01 = *(const uint4*)&sW1p[((wn*4 + ks)*2 + 0)*128 + lane*4];
            uint4 b23 = *(const uint4*)&sW1p[((wn*4 + ks)*2 + 1)*128 + lane*4];
            mma8(acc[0], a, b01.x, b01.y);
            mma8(acc[1], a, b01.z, b01.w);
            mma8(acc[2], a, b23.x, b23.y);
            mma8(acc[3], a, b23.z, b23.w);
        }
        #pragma unroll
        for (int nt = 0; nt < 4; nt++) {
            int c = wn*32 + nt*8 + tig*2;
            *(uint2*)&sH1[e1*132 + c] =
                make_uint2(f2tf(fmaxf(acc[nt][0], 0.f)), f2tf(fmaxf(acc[nt][1], 0.f)));
            *(uint2*)&sH1[e2*132 + c] =
                make_uint2(f2tf(fmaxf(acc[nt][2], 0.f)), f2tf(fmaxf(acc[nt][3], 0.f)));
        }
        __syncthreads();

        // ---- GEMM2: EN = H1 @ W2 + b2  (K=128, N=64) → outE vectorized ----
        float acc2[2][4];
        {
            float4 b = *(const float4*)&sB2[wn*16 + tig*4];
            acc2[0][0] = b.x; acc2[0][1] = b.y; acc2[1][0] = b.z; acc2[1][1] = b.w;
            acc2[0][2] = b.x; acc2[0][3] = b.y; acc2[1][2] = b.z; acc2[1][3] = b.w;
        }
        #pragma unroll 4
        for (int ks = 0; ks < 16; ks++) {
            uint32_t a[4];
            a[0] = sH1[e1*132 + ks*8 + tig];
            a[1] = sH1[e2*132 + ks*8 + tig];
            a[2] = sH1[e1*132 + ks*8 + tig + 4];
            a[3] = sH1[e2*132 + ks*8 + tig + 4];
            uint4 b = *(const uint4*)&sW2p[(wn*16 + ks)*128 + lane*4];
            mma8(acc2[0], a, b.x, b.y);
            mma8(acc2[1], a, b.z, b.w);
        }
        *(float4*)&outE[(size_t)(e0 + e1)*64 + wn*16 + tig*4] =
            make_float4(acc2[0][0], acc2[0][1], acc2[1][0], acc2[1][1]);
        *(float4*)&outE[(size_t)(e0 + e2)*64 + wn*16 + tig*4] =
            make_float4(acc2[0][2], acc2[0][3], acc2[1][2], acc2[1][3]);
    }
}

// ================= K2b: message MLP via tf32 mma.sync — 1024 thr, staged EN, paired-B =================
// words: sW3p 8192 | sW4p 16384 | sEN 8704 | sH2 16896 | sB4 128 | idx 256
#define S2B_SMEM ((8192 + 16384 + 8704 + 16896 + 128 + 256) * 4)
__global__ void __launch_bounds__(1024, 1)
k2b(const float* __restrict__ n1w1, const float* __restrict__ n1w2,
    const float* __restrict__ n1b2,
    const int* __restrict__ ei, const float* __restrict__ edgeNew) {
    extern __shared__ float sm[];
    uint32_t* sW3p = (uint32_t*)sm;              // [((wn*8+ks)*2+pr)][128]
    uint32_t* sW4p = (uint32_t*)(sm + 8192);     // [((wn*16+ks)*2+pr)][128]
    uint32_t* sEN  = (uint32_t*)(sm + 24576);    // [128e][68]
    uint32_t* sH2  = (uint32_t*)(sm + 33280);    // [128e][132]
    float*    sB4  = sm + 50176;                 // 128
    int* sRow = (int*)(sm + 50304);
    int* sCol = sRow + 128;

    int tid = threadIdx.x, lane = tid & 31, w = tid >> 5;
    int wm = w & 7, wn = w >> 3;
    int g = lane >> 2, tig = lane & 3;
    int e1 = wm*16 + g, e2 = e1 + 8;

    // ---- W3^T paired: i = ((wn*8+ks)*2+pr)*128 + lane*4 + q ----
    for (int i = tid; i < 8192; i += 1024) {
        int q = i & 3, ln = (i >> 2) & 31, pr = (i >> 7) & 1;
        int ks = (i >> 8) & 7, wn_ = (i >> 11) & 3;
        int nt = pr*2 + (q >> 1), h = q & 1;
        int gnt = wn_*4 + nt, p = ln >> 2;
        int n_orig = (gnt >> 2)*32 + (p >> 1)*8 + (gnt & 3)*2 + (p & 1);
        int k = ks*8 + (ln & 3) + h*4;
        sW3p[i] = f2tf(n1w1[(64 + k)*128 + n_orig]);
    }
    // ---- W4^T paired: i = ((wn*16+ks)*2+pr)*128 + lane*4 + q ----
    for (int i = tid; i < 16384; i += 1024) {
        int q = i & 3, ln = (i >> 2) & 31, pr = (i >> 7) & 1;
        int ks = (i >> 8) & 15, wn_ = (i >> 12) & 3;
        int nt = pr*2 + (q >> 1), h = q & 1;
        int gnt = wn_*4 + nt, p = ln >> 2;
        int v = ks*8 + (ln & 3) + h*4;
        int k_orig = PHI32(v);
        int n = gnt*8 + p;
        sW4p[i] = f2tf(n1w2[k_orig*128 + n]);
    }
    if (tid < 128) sB4[tid] = n1b2[tid];

    for (int t = blockIdx.x; t < NTILE; t += gridDim.x) {
        __syncthreads();
        int e0 = t * 128;
        if (tid < 128) {
            sRow[tid] = ei[e0 + tid];
            sCol[tid] = ei[NE + e0 + tid];
        }
        for (int i = tid; i < 2048; i += 1024) {  // stage EN [128][64] tf32, stride 68
            int e = i >> 4, kc = i & 15;
            float4 v = *(const float4*)&edgeNew[(size_t)(e0 + e)*64 + kc*4];
            *(uint4*)&sEN[e*68 + kc*4] = make_uint4(f2tf(v.x), f2tf(v.y), f2tf(v.z), f2tf(v.w));
        }
        __syncthreads();

        int r1 = sRow[e1], r2 = sRow[e2];
        int c1 = sCol[e1], c2 = sCol[e2];

        // ---- GEMM3 seeds: Ms[row] (contiguous float4 pairs) ----
        float acc[4][4];
        {
            const float4* M1 = (const float4*)&d_Ms[(size_t)r1*128 + wn*32 + tig*8];
            const float4* M2 = (const float4*)&d_Ms[(size_t)r2*128 + wn*32 + tig*8];
            float4 a0 = M1[0], a1 = M1[1], b0 = M2[0], b1 = M2[1];
            acc[0][0] = a0.x; acc[0][1] = a0.y; acc[1][0] = a0.z; acc[1][1] = a0.w;
            acc[2][0] = a1.x; acc[2][1] = a1.y; acc[3][0] = a1.z; acc[3][1] = a1.w;
            acc[0][2] = b0.x; acc[0][3] = b0.y; acc[1][2] = b0.z; acc[1][3] = b0.w;
            acc[2][2] = b1.x; acc[2][3] = b1.y; acc[3][2] = b1.z; acc[3][3] = b1.w;
        }
        // ---- GEMM3: += EN @ W3  (K=64, A staged in smem) ----
        #pragma unroll
        for (int ks = 0; ks < 8; ks++) {
            uint32_t a[4];
            a[0] = sEN[e1*68 + ks*8 + tig];
            a[1] = sEN[e2*68 + ks*8 + tig];
            a[2] = sEN[e1*68 + ks*8 + tig + 4];
            a[3] = sEN[e2*68 + ks*8 + tig + 4];
            uint4 b01 = *(const uint4*)&sW3p[((wn*8 + ks)*2 + 0)*128 + lane*4];
            uint4 b23 = *(const uint4*)&sW3p[((wn*8 + ks)*2 + 1)*128 + lane*4];
            mma8(acc[0], a, b01.x, b01.y);
            mma8(acc[1], a, b01.z, b01.w);
            mma8(acc[2], a, b23.x, b23.y);
            mma8(acc[3], a, b23.z, b23.w);
        }
        #pragma unroll
        for (int nt = 0; nt < 4; nt++) {
            int c = wn*32 + nt*8 + tig*2;
            *(uint2*)&sH2[e1*132 + c] =
                make_uint2(f2tf(fmaxf(acc[nt][0], 0.f)), f2tf(fmaxf(acc[nt][1], 0.f)));
            *(uint2*)&sH2[e2*132 + c] =
                make_uint2(f2tf(fmaxf(acc[nt][2], 0.f)), f2tf(fmaxf(acc[nt][3], 0.f)));
        }
        __syncthreads();

        // ---- GEMM4: m = H2 @ W4 + b4  (K=128, N=128) → v4 scatter (agg pi space) ----
        float acc4[4][4];
        #pragma unroll
        for (int nt = 0; nt < 4; nt++) {
            int c = wn*32 + nt*8 + tig*2;
            acc4[nt][0] = sB4[c]; acc4[nt][1] = sB4[c+1];
            acc4[nt][2] = sB4[c]; acc4[nt][3] = sB4[c+1];
        }
        #pragma unroll 4
        for (int ks = 0; ks < 16; ks++) {
            uint32_t a[4];
            a[0] = sH2[e1*132 + ks*8 + tig];
            a[1] = sH2[e2*132 + ks*8 + tig];
            a[2] = sH2[e1*132 + ks*8 + tig + 4];
            a[3] = sH2[e2*132 + ks*8 + tig + 4];
            uint4 b01 = *(const uint4*)&sW4p[((wn*16 + ks)*2 + 0)*128 + lane*4];
            uint4 b23 = *(const uint4*)&sW4p[((wn*16 + ks)*2 + 1)*128 + lane*4];
            mma8(acc4[0], a, b01.x, b01.y);
            mma8(acc4[1], a, b01.z, b01.w);
            mma8(acc4[2], a, b23.x, b23.y);
            mma8(acc4[3], a, b23.z, b23.w);
        }
        {
            float* b1p = &d_agg[(size_t)c1*128 + wn*32 + tig*8];
            red_add_v4f(b1p,     acc4[0][0], acc4[0][1], acc4[1][0], acc4[1][1]);
            red_add_v4f(b1p + 4, acc4[2][0], acc4[2][1], acc4[3][0], acc4[3][1]);
            float* b2p = &d_agg[(size_t)c2*128 + wn*32 + tig*8];
            red_add_v4f(b2p,     acc4[0][2], acc4[0][3], acc4[1][2], acc4[1][3]);
            red_add_v4f(b2p + 4, acc4[2][2], acc4[2][3], acc4[3][2], acc4[3][3]);
        }
    }
}

// ---------------- K3: node MLP2 + pooling (SIMT f32x2; un-permutes agg) ----------------
#define NODE_SMEM (49280 * 4)
__global__ void __launch_bounds__(512, 1)
k_node(const float* __restrict__ x, const float* __restrict__ u,
       const float* __restrict__ n2w1, const float* __restrict__ n2b1,
       const float* __restrict__ n2w2, const float* __restrict__ n2b2,
       const int* __restrict__ batch, float* __restrict__ outX) {
    extern __shared__ float sm[];
    float* sW1  = sm;
    float* sW2  = sm + 26624;
    float* sB1  = sm + 34816;
    float* sB2  = sm + 34944;
    float* sInT = sm + 35008;
    float* sInv = sm + 49152;
    int*   sBat = (int*)(sm + 49216);

    int tid = threadIdx.x, tx = tid & 31, wid = tid >> 5;
    int ty = wid & 7, fh = wid >> 3;
    int fbase = fh*64 + tx*2;
    int f2 = fh*32 + tx;

    for (int i = tid; i < 26624; i += 512) sW1[i] = n2w1[i];
    for (int i = tid; i < 8192;  i += 512) sW2[i] = n2w2[i];
    if (tid < 128) sB1[tid] = n2b1[tid];
    if (tid < 64)  sB2[tid] = n2b2[tid];

    int n0 = blockIdx.x * 64;
    if (tid < 64) {
        int n = n0 + tid;
        if (n < NN) { sBat[tid] = batch[n]; sInv[tid] = 1.f / fmaxf(d_deg[n], 1.f); }
        else        { sBat[tid] = 0;        sInv[tid] = 0.f; }
    }
    __syncthreads();
    for (int idx = tid; idx < 64*64; idx += 512) {
        int node = idx >> 6, k = idx & 63; int n = n0 + node;
        sInT[k*68 + node] = (n < NN) ? x[(size_t)n*64 + k] : 0.f;
    }
    for (int idx = tid; idx < 64*128; idx += 512) {
        int node = idx >> 7, k = idx & 127; int n = n0 + node;
        sInT[(64 + k)*68 + node] = (n < NN) ? d_agg[(size_t)n*128 + PHI32(k)] * sInv[node] : 0.f;
    }
    for (int idx = tid; idx < 64*16; idx += 512) {
        int node = idx >> 4, k = idx & 15;
        sInT[(192 + k)*68 + node] = u[sBat[node]*16 + k];
    }
    __syncthreads();

    ull acc[4][2];
    #pragma unroll
    for (int p = 0; p < 4; p++) {
        acc[p][0] = pack2(sB1[fbase],     sB1[fbase]);
        acc[p][1] = pack2(sB1[fbase + 1], sB1[fbase + 1]);
    }
    #pragma unroll 4
    for (int k = 0; k < 208; k++) {
        float2 B = *(const float2*)&sW1[k*128 + fbase];
        ull bb0 = pack2(B.x, B.x), bb1 = pack2(B.y, B.y);
        float4 A0 = *(const float4*)&sInT[k*68 + ty*8];
        float4 A1 = *(const float4*)&sInT[k*68 + ty*8 + 4];
        ull a0 = pack2(A0.x, A0.y), a1 = pack2(A0.z, A0.w);
        ull a2 = pack2(A1.x, A1.y), a3 = pack2(A1.z, A1.w);
        ffma2(acc[0][0], a0, bb0); ffma2(acc[0][1], a0, bb1);
        ffma2(acc[1][0], a1, bb0); ffma2(acc[1][1], a1, bb1);
        ffma2(acc[2][0], a2, bb0); ffma2(acc[2][1], a2, bb1);
        ffma2(acc[3][0], a3, bb0); ffma2(acc[3][1], a3, bb1);
    }
    __syncthreads();
    #pragma unroll
    for (int p = 0; p < 4; p++) {
        *(ull*)&sInT[(fbase + 0)*68 + ty*8 + 2*p] = relu2(acc[p][0]);
        *(ull*)&sInT[(fbase + 1)*68 + ty*8 + 2*p] = relu2(acc[p][1]);
    }
    __syncthreads();

    ull acc2[4];
    {
        float b = sB2[f2];
        #pragma unroll
        for (int p = 0; p < 4; p++) acc2[p] = pack2(b, b);
    }
    #pragma unroll 4
    for (int k = 0; k < 128; k++) {
        float bs = sW2[k*64 + f2];
        ull bb = pack2(bs, bs);
        float4 A0 = *(const float4*)&sInT[k*68 + ty*8];
        float4 A1 = *(const float4*)&sInT[k*68 + ty*8 + 4];
        ffma2(acc2[0], pack2(A0.x, A0.y), bb);
        ffma2(acc2[1], pack2(A0.z, A0.w), bb);
        ffma2(acc2[2], pack2(A1.x, A1.y), bb);
        ffma2(acc2[3], pack2(A1.z, A1.w), bb);
    }
    #pragma unroll
    for (int p = 0; p < 4; p++) {
        float2 v = unpack2(acc2[p]);
        int node = ty*8 + 2*p;
        int n_lo = n0 + node;
        if (n_lo < NN) {
            outX[(size_t)n_lo*64 + f2] = v.x;
            red_add_f(&d_gsum[sBat[node]*64 + f2], v.x);
        }
        if (n_lo + 1 < NN) {
            outX[(size_t)(n_lo+1)*64 + f2] = v.y;
            red_add_f(&d_gsum[sBat[node+1]*64 + f2], v.y);
        }
    }
}

// ---------------- K4: global MLP ----------------
__global__ void k_glob(const float* __restrict__ u,
                       const float* __restrict__ gw1, const float* __restrict__ gb1,
                       const float* __restrict__ gw2, const float* __restrict__ gb2,
                       float* __restrict__ outU) {
    __shared__ float sin[80];
    __shared__ float sh[128];
    int g = blockIdx.x, tid = threadIdx.x;
    if (tid < 16) sin[tid] = u[g*16 + tid];
    if (tid < 64) {
        float c = fmaxf(d_gcnt[g], 1.f);
        sin[16 + tid] = d_gsum[g*64 + tid] / c;
    }
    __syncthreads();
    float acc = gb1[tid];
    #pragma unroll 8
    for (int k = 0; k < 80; k++) acc += sin[k] * gw1[k*128 + tid];
    sh[tid] = fmaxf(acc, 0.f);
    __syncthreads();
    if (tid < 32) {
        float a2 = gb2[tid];
        #pragma unroll 8
        for (int k = 0; k < 128; k++) a2 += sh[k] * gw2[k*32 + tid];
        outU[g*32 + tid] = a2;
    }
}

// ---------------- launch ----------------
extern "C" void kernel_launch(void* const* d_in, const int* in_sizes, int n_in,
                              void* d_out, int out_size) {
    const float* x     = (const float*)d_in[0];
    const float* ea    = (const float*)d_in[1];
    const float* u     = (const float*)d_in[2];
    const float* ew1   = (const float*)d_in[3];
    const float* eb1   = (const float*)d_in[4];
    const float* ew2   = (const float*)d_in[5];
    const float* eb2   = (const float*)d_in[6];
    const float* n1w1  = (const float*)d_in[7];
    const float* n1b1  = (const float*)d_in[8];
    const float* n1w2  = (const float*)d_in[9];
    const float* n1b2  = (const float*)d_in[10];
    const float* n2w1  = (const float*)d_in[11];
    const float* n2b1  = (const float*)d_in[12];
    const float* n2w2  = (const float*)d_in[13];
    const float* n2b2  = (const float*)d_in[14];
    const float* gw1   = (const float*)d_in[15];
    const float* gb1   = (const float*)d_in[16];
    const float* gw2   = (const float*)d_in[17];
    const float* gb2   = (const float*)d_in[18];
    const int*   ei    = (const int*)d_in[19];
    const int*   batch = (const int*)d_in[20];

    float* out  = (float*)d_out;
    float* outX = out;
    float* outE = out + (size_t)NN*64;
    float* outU = out + (size_t)NN*64 + (size_t)NE*64;

    cudaFuncSetAttribute(k_pre,  cudaFuncAttributeMaxDynamicSharedMemorySize, PRE_SMEM);
    cudaFuncSetAttribute(k2a,    cudaFuncAttributeMaxDynamicSharedMemorySize, S2A_SMEM);
    cudaFuncSetAttribute(k2b,    cudaFuncAttributeMaxDynamicSharedMemorySize, S2B_SMEM);
    cudaFuncSetAttribute(k_node, cudaFuncAttributeMaxDynamicSharedMemorySize, NODE_SMEM);

    k_zero<<<256, 256>>>();
    k_rg<<<(NG*128 + 255)/256, 256>>>(u, ew1);
    k_pre<<<(NN + 63)/64, 512, PRE_SMEM>>>(x, ew1, eb1, n1w1, n1b1, batch);
    k2a<<<PGRID, 1024, S2A_SMEM>>>(ea, ew1, ew2, eb2, ei, outE);
    k2b<<<PGRID, 1024, S2B_SMEM>>>(n1w1, n1w2, n1b2, ei, outE);
    k_count<<<(NE + 255)/256, 256>>>(ei, batch);
    k_node<<<(NN + 63)/64, 512, NODE_SMEM>>>(x, u, n2w1, n2b1, n2w2, n2b2, batch, outX);
    k_glob<<<NG, 128>>>(u, gw1, gb1, gw2, gb2, outU);
}

// round 10
// speedup vs baseline: 1.1446x; 1.0699x over previous
#include <cuda_runtime.h>
#include <cstdint>

#define NN 50000
#define NE 800000
#define NG 256
#define NTILE 6250          // NE / 128
#define PGRID 152

typedef unsigned long long ull;

// PHI: involutive permutation within 32-blocks (fragment<->original col map)
__host__ __device__ __forceinline__ int PHI32(int v) {
    return (v & ~31) | (((v >> 1) & 3) << 3) | (((v >> 3) & 3) << 1) | (v & 1);
}

// ---------------- tf32 mma.sync helpers ----------------
__device__ __forceinline__ uint32_t f2tf(float f) {
    uint32_t r; asm("cvt.rna.tf32.f32 %0, %1;" : "=r"(r) : "f"(f)); return r;
}
__device__ __forceinline__ void mma8(float* d, const uint32_t* a, uint32_t b0, uint32_t b1) {
    asm volatile("mma.sync.aligned.m16n8k8.row.col.f32.tf32.tf32.f32 "
        "{%0,%1,%2,%3},{%4,%5,%6,%7},{%8,%9},{%0,%1,%2,%3};"
        : "+f"(d[0]), "+f"(d[1]), "+f"(d[2]), "+f"(d[3])
        : "r"(a[0]), "r"(a[1]), "r"(a[2]), "r"(a[3]), "r"(b0), "r"(b1));
}

// ---------------- f32x2 helpers ----------------
__device__ __forceinline__ void ffma2(ull &d, ull a, ull b) {
    asm("fma.rn.f32x2 %0, %1, %2, %0;" : "+l"(d) : "l"(a), "l"(b));
}
__device__ __forceinline__ ull pack2(float lo, float hi) {
    ull r; asm("mov.b64 %0, {%1, %2};" : "=l"(r) : "f"(lo), "f"(hi)); return r;
}
__device__ __forceinline__ float2 unpack2(ull v) {
    float2 r; asm("mov.b64 {%0, %1}, %2;" : "=f"(r.x), "=f"(r.y) : "l"(v)); return r;
}
__device__ __forceinline__ ull relu2(ull v) {
    float2 t = unpack2(v);
    return pack2(fmaxf(t.x, 0.f), fmaxf(t.y, 0.f));
}
__device__ __forceinline__ void red_add_v4f(float* p, float a, float b, float c, float d) {
    asm volatile("red.global.add.v4.f32 [%0], {%1,%2,%3,%4};" :: "l"(p), "f"(a), "f"(b), "f"(c), "f"(d) : "memory");
}
__device__ __forceinline__ void red_add_f(float* p, float a) {
    asm volatile("red.global.add.f32 [%0], %1;" :: "l"(p), "f"(a) : "memory");
}

// ---------------- device scratch ----------------
__device__ float d_P [NN*128];   // P + Rg[batch[n]] + eb1  (PR-fused)
__device__ float d_Q [NN*128];
__device__ float d_Ms[NN*128];
__device__ float d_Rg[NG*128];
__device__ float d_agg[NN*128];  // PHI-permuted column layout
__device__ float d_deg[NN];
__device__ float d_gsum[NG*64];
__device__ float d_gcnt[NG];

// ---------------- K0 / K0b ----------------
__global__ void k_zero() {
    int i = blockIdx.x * blockDim.x + threadIdx.x;
    int stride = gridDim.x * blockDim.x;
    for (int idx = i; idx < NN*128; idx += stride) d_agg[idx] = 0.f;
    for (int idx = i; idx < NN;     idx += stride) d_deg[idx] = 0.f;
    for (int idx = i; idx < NG*64;  idx += stride) d_gsum[idx] = 0.f;
    for (int idx = i; idx < NG;     idx += stride) d_gcnt[idx] = 0.f;
}
__global__ void k_count(const int* __restrict__ ei, const int* __restrict__ batch) {
    int i = blockIdx.x * blockDim.x + threadIdx.x;
    if (i < NE) atomicAdd(&d_deg[ei[NE + i]], 1.f);
    if (i < NN) atomicAdd(&d_gcnt[batch[i]], 1.f);
}

// ---------------- K1b: R = u @ e_w1[160:176]  (runs BEFORE k_pre) ----------------
__global__ void k_rg(const float* __restrict__ u, const float* __restrict__ ew1) {
    int i = blockIdx.x * blockDim.x + threadIdx.x;
    if (i < NG*128) {
        int g = i >> 7, j = i & 127;
        float acc = 0.f;
        #pragma unroll
        for (int k = 0; k < 16; k++) acc += u[g*16 + k] * ew1[(160 + k)*128 + j];
        d_Rg[i] = acc;
    }
}

// ---------------- K1: precompute PR, Q, Msrc (SIMT f32x2, fp32-exact) ----------------
#define PRE_SMEM ((4352 + 3*8192 + 256 + 64) * 4)
__global__ void __launch_bounds__(512, 1)
k_pre(const float* __restrict__ x, const float* __restrict__ ew1,
      const float* __restrict__ eb1, const float* __restrict__ n1w1,
      const float* __restrict__ n1b1, const int* __restrict__ batch) {
    extern __shared__ float sm[];
    float* sXT  = sm;
    float* sWa  = sm + 4352;
    float* sWb  = sWa + 8192;
    float* sWm  = sWb + 8192;
    float* sEb1 = sWm + 8192;
    float* sNb1 = sEb1 + 128;
    int*   sBat = (int*)(sNb1 + 128);
    int tid = threadIdx.x;
    for (int i = tid; i < 8192; i += 512) {
        sWa[i] = ew1[i];
        sWb[i] = ew1[64*128 + i];
        sWm[i] = n1w1[i];
    }
    if (tid < 128) { sEb1[tid] = eb1[tid]; sNb1[tid] = n1b1[tid]; }
    int n0 = blockIdx.x * 64;
    if (tid < 64) {
        int n = n0 + tid;
        sBat[tid] = (n < NN) ? batch[n] : 0;
    }
    for (int idx = tid; idx < 64*64; idx += 512) {
        int node = idx >> 6, k = idx & 63;
        int n = n0 + node;
        sXT[k*68 + node] = (n < NN) ? x[(size_t)n*64 + k] : 0.f;
    }
    __syncthreads();
    int tx = tid & 31, wid = tid >> 5;
    int ty = wid & 7, fh = wid >> 3;
    int fbase = fh*64 + tx*2;
    for (int which = 0; which < 3; which++) {
        const float* W = (which == 0) ? sWa : (which == 1) ? sWb : sWm;
        ull acc[4][2];
        #pragma unroll
        for (int p = 0; p < 4; p++)
            #pragma unroll
            for (int j = 0; j < 2; j++) {
                float b = (which == 0) ? sEb1[fbase + j] : (which == 2) ? sNb1[fbase + j] : 0.f;
                acc[p][j] = pack2(b, b);
            }
        #pragma unroll 4
        for (int k = 0; k < 64; k++) {
            float2 B = *(const float2*)&W[k*128 + fbase];
            ull bb0 = pack2(B.x, B.x), bb1 = pack2(B.y, B.y);
            float4 A0 = *(const float4*)&sXT[k*68 + ty*8];
            float4 A1 = *(const float4*)&sXT[k*68 + ty*8 + 4];
            ull a0 = pack2(A0.x, A0.y), a1 = pack2(A0.z, A0.w);
            ull a2 = pack2(A1.x, A1.y), a3 = pack2(A1.z, A1.w);
            ffma2(acc[0][0], a0, bb0); ffma2(acc[0][1], a0, bb1);
            ffma2(acc[1][0], a1, bb0); ffma2(acc[1][1], a1, bb1);
            ffma2(acc[2][0], a2, bb0); ffma2(acc[2][1], a2, bb1);
            ffma2(acc[3][0], a3, bb0); ffma2(acc[3][1], a3, bb1);
        }
        float* dst = (which == 0) ? d_P : (which == 1) ? d_Q : d_Ms;
        #pragma unroll
        for (int p = 0; p < 4; p++) {
            float2 v0 = unpack2(acc[p][0]), v1 = unpack2(acc[p][1]);
            int node = ty*8 + 2*p;
            int n_lo = n0 + node;
            if (which == 0) {   // PR-fuse
                if (n_lo < NN) {
                    const float* rg = &d_Rg[(size_t)sBat[node]*128 + fbase];
                    v0.x += rg[0]; v1.x += rg[1];
                }
                if (n_lo + 1 < NN) {
                    const float* rg = &d_Rg[(size_t)sBat[node+1]*128 + fbase];
                    v0.y += rg[0]; v1.y += rg[1];
                }
            }
            if (n_lo < NN)
                *(float2*)&dst[(size_t)n_lo*128 + fbase] = make_float2(v0.x, v1.x);
            if (n_lo + 1 < NN)
                *(float2*)&dst[(size_t)(n_lo+1)*128 + fbase] = make_float2(v0.y, v1.y);
        }
    }
}

// ================= K2a: EdgeModel via tf32 mma.sync — 1024 thr, staged EA, paired-B =================
// words: sW1p 4096 | sW2p 8192 | sEA 4608 | sH1 128*132 | sB2 64 | idx 256
#define S2A_SMEM ((4096 + 8192 + 4608 + 16896 + 64 + 256) * 4)
__global__ void __launch_bounds__(1024, 1)
k2a(const float* __restrict__ ea, const float* __restrict__ ew1,
    const float* __restrict__ ew2, const float* __restrict__ eb2,
    const int* __restrict__ ei, float* __restrict__ outE) {
    extern __shared__ float sm[];
    uint32_t* sW1p = (uint32_t*)sm;              // [((wn*4+ks)*2+pr)][128]
    uint32_t* sW2p = (uint32_t*)(sm + 4096);     // [(wn*16+ks)][128]
    uint32_t* sEA  = (uint32_t*)(sm + 12288);    // [128e][36]
    uint32_t* sH1  = (uint32_t*)(sm + 16896);    // [128e][132]
    float*    sB2  = sm + 33792;                 // 64
    int* sRow = (int*)(sm + 33856);
    int* sCol = sRow + 128;

    int tid = threadIdx.x, lane = tid & 31, w = tid >> 5;
    int wm = w & 7, wn = w >> 3;
    int g = lane >> 2, tig = lane & 3;
    int e1 = wm*16 + g, e2 = e1 + 8;

    // ---- W1c^T paired layout: i = ((wn*4+ks)*2+pr)*128 + lane*4 + q ----
    for (int i = tid; i < 4096; i += 1024) {
        int q = i & 3, ln = (i >> 2) & 31, pr = (i >> 7) & 1;
        int ks = (i >> 8) & 3, wn_ = (i >> 10) & 3;
        int nt = pr*2 + (q >> 1), h = q & 1;
        int gnt = wn_*4 + nt, p = ln >> 2;
        int n_orig = (gnt >> 2)*32 + (p >> 1)*8 + (gnt & 3)*2 + (p & 1);
        int k = ks*8 + (ln & 3) + h*4;
        sW1p[i] = f2tf(ew1[(128 + k)*128 + n_orig]);
    }
    // ---- W2^T paired: i = (wn*16+ks)*128 + lane*4 + q ----
    for (int i = tid; i < 8192; i += 1024) {
        int q = i & 3, ln = (i >> 2) & 31;
        int ks = (i >> 7) & 15, wn_ = (i >> 11) & 3;
        int nt = q >> 1, h = q & 1;
        int gnt = wn_*2 + nt, p = ln >> 2;
        int n_orig = (gnt >> 1)*16 + (p >> 1)*4 + (gnt & 1)*2 + (p & 1);
        int k_orig = PHI32(ks*8 + (ln & 3) + h*4);
        sW2p[i] = f2tf(ew2[k_orig*64 + n_orig]);
    }
    if (tid < 64) sB2[tid] = eb2[tid];

    for (int t = blockIdx.x; t < NTILE; t += gridDim.x) {
        __syncthreads();
        int e0 = t * 128;
        if (tid < 128) {
            sRow[tid] = ei[e0 + tid];
            sCol[tid] = ei[NE + e0 + tid];
        }
        {   // stage EA [128][32] tf32, stride 36 (coalesced; exactly 1024 uint4 chunks)
            int e = tid >> 3, kc = tid & 7;
            float4 v = *(const float4*)&ea[(size_t)(e0 + e)*32 + kc*4];
            *(uint4*)&sEA[e*36 + kc*4] = make_uint4(f2tf(v.x), f2tf(v.y), f2tf(v.z), f2tf(v.w));
        }
        __syncthreads();

        int r1 = sRow[e1], cc1 = sCol[e1];
        int r2 = sRow[e2], cc2 = sCol[e2];

        // ---- GEMM1 seeds: PR[row] + Q[col] (contiguous float4 pairs) ----
        float acc[4][4];
        {
            const float4* P1 = (const float4*)&d_P[(size_t)r1*128 + wn*32 + tig*8];
            const float4* Q1 = (const float4*)&d_Q[(size_t)cc1*128 + wn*32 + tig*8];
            const float4* P2 = (const float4*)&d_P[(size_t)r2*128 + wn*32 + tig*8];
            const float4* Q2 = (const float4*)&d_Q[(size_t)cc2*128 + wn*32 + tig*8];
            float4 a0 = P1[0], b0 = Q1[0], a1 = P1[1], b1 = Q1[1];
            float4 c0 = P2[0], d0 = Q2[0], c1 = P2[1], d1 = Q2[1];
            acc[0][0] = a0.x + b0.x; acc[0][1] = a0.y + b0.y;
            acc[1][0] = a0.z + b0.z; acc[1][1] = a0.w + b0.w;
            acc[2][0] = a1.x + b1.x; acc[2][1] = a1.y + b1.y;
            acc[3][0] = a1.z + b1.z; acc[3][1] = a1.w + b1.w;
            acc[0][2] = c0.x + d0.x; acc[0][3] = c0.y + d0.y;
            acc[1][2] = c0.z + d0.z; acc[1][3] = c0.w + d0.w;
            acc[2][2] = c1.x + d1.x; acc[2][3] = c1.y + d1.y;
            acc[3][2] = c1.z + d1.z; acc[3][3] = c1.w + d1.w;
        }
        // ---- GEMM1: += EA @ W1c  (K=32, A staged in smem; conflict-free 4g+tig banks) ----
        #pragma unroll
        for (int ks = 0; ks < 4; ks++) {
            uint32_t a[4];
            a[0] = sEA[e1*36 + ks*8 + tig];
            a[1] = sEA[e2*36 + ks*8 + tig];
            a[2] = sEA[e1*36 + ks*8 + tig + 4];
            a[3] = sEA[e2*36 + ks*8 + tig + 4];
            uint4 b01 = *(const uint4*)&sW1p[((wn*4 + ks)*2 + 0)*128 + lane*4];
            uint4 b23 = *(const uint4*)&sW1p[((wn*4 + ks)*2 + 1)*128 + lane*4];
            mma8(acc[0], a, b01.x, b01.y);
            mma8(acc[1], a, b01.z, b01.w);
            mma8(acc[2], a, b23.x, b23.y);
            mma8(acc[3], a, b23.z, b23.w);
        }
        #pragma unroll
        for (int nt = 0; nt < 4; nt++) {
            int c = wn*32 + nt*8 + tig*2;
            *(uint2*)&sH1[e1*132 + c] =
                make_uint2(f2tf(fmaxf(acc[nt][0], 0.f)), f2tf(fmaxf(acc[nt][1], 0.f)));
            *(uint2*)&sH1[e2*132 + c] =
                make_uint2(f2tf(fmaxf(acc[nt][2], 0.f)), f2tf(fmaxf(acc[nt][3], 0.f)));
        }
        __syncthreads();

        // ---- GEMM2: EN = H1 @ W2 + b2  (K=128, N=64) → outE vectorized ----
        float acc2[2][4];
        {
            float4 b = *(const float4*)&sB2[wn*16 + tig*4];
            acc2[0][0] = b.x; acc2[0][1] = b.y; acc2[1][0] = b.z; acc2[1][1] = b.w;
            acc2[0][2] = b.x; acc2[0][3] = b.y; acc2[1][2] = b.z; acc2[1][3] = b.w;
        }
        #pragma unroll 4
        for (int ks = 0; ks < 16; ks++) {
            uint32_t a[4];
            a[0] = sH1[e1*132 + ks*8 + tig];
            a[1] = sH1[e2*132 + ks*8 + tig];
            a[2] = sH1[e1*132 + ks*8 + tig + 4];
            a[3] = sH1[e2*132 + ks*8 + tig + 4];
            uint4 b = *(const uint4*)&sW2p[(wn*16 + ks)*128 + lane*4];
            mma8(acc2[0], a, b.x, b.y);
            mma8(acc2[1], a, b.z, b.w);
        }
        *(float4*)&outE[(size_t)(e0 + e1)*64 + wn*16 + tig*4] =
            make_float4(acc2[0][0], acc2[0][1], acc2[1][0], acc2[1][1]);
        *(float4*)&outE[(size_t)(e0 + e2)*64 + wn*16 + tig*4] =
            make_float4(acc2[0][2], acc2[0][3], acc2[1][2], acc2[1][3]);
    }
}

// ================= K2b: message MLP via tf32 mma.sync — 1024 thr, staged EN, paired-B =================
// words: sW3p 8192 | sW4p 16384 | sEN 8704 | sH2 16896 | sB4 128 | idx 256
#define S2B_SMEM ((8192 + 16384 + 8704 + 16896 + 128 + 256) * 4)
__global__ void __launch_bounds__(1024, 1)
k2b(const float* __restrict__ n1w1, const float* __restrict__ n1w2,
    const float* __restrict__ n1b2,
    const int* __restrict__ ei, const float* __restrict__ edgeNew) {
    extern __shared__ float sm[];
    uint32_t* sW3p = (uint32_t*)sm;              // [((wn*8+ks)*2+pr)][128]
    uint32_t* sW4p = (uint32_t*)(sm + 8192);     // [((wn*16+ks)*2+pr)][128]
    uint32_t* sEN  = (uint32_t*)(sm + 24576);    // [128e][68]
    uint32_t* sH2  = (uint32_t*)(sm + 33280);    // [128e][132]
    float*    sB4  = sm + 50176;                 // 128
    int* sRow = (int*)(sm + 50304);
    int* sCol = sRow + 128;

    int tid = threadIdx.x, lane = tid & 31, w = tid >> 5;
    int wm = w & 7, wn = w >> 3;
    int g = lane >> 2, tig = lane & 3;
    int e1 = wm*16 + g, e2 = e1 + 8;

    // ---- W3^T paired: i = ((wn*8+ks)*2+pr)*128 + lane*4 + q ----
    for (int i = tid; i < 8192; i += 1024) {
        int q = i & 3, ln = (i >> 2) & 31, pr = (i >> 7) & 1;
        int ks = (i >> 8) & 7, wn_ = (i >> 11) & 3;
        int nt = pr*2 + (q >> 1), h = q & 1;
        int gnt = wn_*4 + nt, p = ln >> 2;
        int n_orig = (gnt >> 2)*32 + (p >> 1)*8 + (gnt & 3)*2 + (p & 1);
        int k = ks*8 + (ln & 3) + h*4;
        sW3p[i] = f2tf(n1w1[(64 + k)*128 + n_orig]);
    }
    // ---- W4^T paired: i = ((wn*16+ks)*2+pr)*128 + lane*4 + q ----
    for (int i = tid; i < 16384; i += 1024) {
        int q = i & 3, ln = (i >> 2) & 31, pr = (i >> 7) & 1;
        int ks = (i >> 8) & 15, wn_ = (i >> 12) & 3;
        int nt = pr*2 + (q >> 1), h = q & 1;
        int gnt = wn_*4 + nt, p = ln >> 2;
        int v = ks*8 + (ln & 3) + h*4;
        int k_orig = PHI32(v);
        int n = gnt*8 + p;
        sW4p[i] = f2tf(n1w2[k_orig*128 + n]);
    }
    if (tid < 128) sB4[tid] = n1b2[tid];

    for (int t = blockIdx.x; t < NTILE; t += gridDim.x) {
        __syncthreads();
        int e0 = t * 128;
        if (tid < 128) {
            sRow[tid] = ei[e0 + tid];
            sCol[tid] = ei[NE + e0 + tid];
        }
        for (int i = tid; i < 2048; i += 1024) {  // stage EN [128][64] tf32, stride 68
            int e = i >> 4, kc = i & 15;
            float4 v = *(const float4*)&edgeNew[(size_t)(e0 + e)*64 + kc*4];
            *(uint4*)&sEN[e*68 + kc*4] = make_uint4(f2tf(v.x), f2tf(v.y), f2tf(v.z), f2tf(v.w));
        }
        __syncthreads();

        int r1 = sRow[e1], r2 = sRow[e2];
        int c1 = sCol[e1], c2 = sCol[e2];

        // ---- GEMM3 seeds: Ms[row] (contiguous float4 pairs) ----
        float acc[4][4];
        {
            const float4* M1 = (const float4*)&d_Ms[(size_t)r1*128 + wn*32 + tig*8];
            const float4* M2 = (const float4*)&d_Ms[(size_t)r2*128 + wn*32 + tig*8];
            float4 a0 = M1[0], a1 = M1[1], b0 = M2[0], b1 = M2[1];
            acc[0][0] = a0.x; acc[0][1] = a0.y; acc[1][0] = a0.z; acc[1][1] = a0.w;
            acc[2][0] = a1.x; acc[2][1] = a1.y; acc[3][0] = a1.z; acc[3][1] = a1.w;
            acc[0][2] = b0.x; acc[0][3] = b0.y; acc[1][2] = b0.z; acc[1][3] = b0.w;
            acc[2][2] = b1.x; acc[2][3] = b1.y; acc[3][2] = b1.z; acc[3][3] = b1.w;
        }
        // ---- GEMM3: += EN @ W3  (K=64, A staged in smem) ----
        #pragma unroll
        for (int ks = 0; ks < 8; ks++) {
            uint32_t a[4];
            a[0] = sEN[e1*68 + ks*8 + tig];
            a[1] = sEN[e2*68 + ks*8 + tig];
            a[2] = sEN[e1*68 + ks*8 + tig + 4];
            a[3] = sEN[e2*68 + ks*8 + tig + 4];
            uint4 b01 = *(const uint4*)&sW3p[((wn*8 + ks)*2 + 0)*128 + lane*4];
            uint4 b23 = *(const uint4*)&sW3p[((wn*8 + ks)*2 + 1)*128 + lane*4];
            mma8(acc[0], a, b01.x, b01.y);
            mma8(acc[1], a, b01.z, b01.w);
            mma8(acc[2], a, b23.x, b23.y);
            mma8(acc[3], a, b23.z, b23.w);
        }
        #pragma unroll
        for (int nt = 0; nt < 4; nt++) {
            int c = wn*32 + nt*8 + tig*2;
            *(uint2*)&sH2[e1*132 + c] =
                make_uint2(f2tf(fmaxf(acc[nt][0], 0.f)), f2tf(fmaxf(acc[nt][1], 0.f)));
            *(uint2*)&sH2[e2*132 + c] =
                make_uint2(f2tf(fmaxf(acc[nt][2], 0.f)), f2tf(fmaxf(acc[nt][3], 0.f)));
        }
        __syncthreads();

        // ---- GEMM4: m = H2 @ W4 + b4  (K=128, N=128) → v4 scatter (agg pi space) ----
        float acc4[4][4];
        #pragma unroll
        for (int nt = 0; nt < 4; nt++) {
            int c = wn*32 + nt*8 + tig*2;
            acc4[nt][0] = sB4[c]; acc4[nt][1] = sB4[c+1];
            acc4[nt][2] = sB4[c]; acc4[nt][3] = sB4[c+1];
        }
        #pragma unroll 4
        for (int ks = 0; ks < 16; ks++) {
            uint32_t a[4];
            a[0] = sH2[e1*132 + ks*8 + tig];
            a[1] = sH2[e2*132 + ks*8 + tig];
            a[2] = sH2[e1*132 + ks*8 + tig + 4];
            a[3] = sH2[e2*132 + ks*8 + tig + 4];
            uint4 b01 = *(const uint4*)&sW4p[((wn*16 + ks)*2 + 0)*128 + lane*4];
            uint4 b23 = *(const uint4*)&sW4p[((wn*16 + ks)*2 + 1)*128 + lane*4];
            mma8(acc4[0], a, b01.x, b01.y);
            mma8(acc4[1], a, b01.z, b01.w);
            mma8(acc4[2], a, b23.x, b23.y);
            mma8(acc4[3], a, b23.z, b23.w);
        }
        {
            float* b1p = &d_agg[(size_t)c1*128 + wn*32 + tig*8];
            red_add_v4f(b1p,     acc4[0][0], acc4[0][1], acc4[1][0], acc4[1][1]);
            red_add_v4f(b1p + 4, acc4[2][0], acc4[2][1], acc4[3][0], acc4[3][1]);
            float* b2p = &d_agg[(size_t)c2*128 + wn*32 + tig*8];
            red_add_v4f(b2p,     acc4[0][2], acc4[0][3], acc4[1][2], acc4[1][3]);
            red_add_v4f(b2p + 4, acc4[2][2], acc4[2][3], acc4[3][2], acc4[3][3]);
        }
    }
}

// ---------------- K3: node MLP2 + pooling (SIMT f32x2; un-permutes agg) ----------------
#define NODE_SMEM (49280 * 4)
__global__ void __launch_bounds__(512, 1)
k_node(const float* __restrict__ x, const float* __restrict__ u,
       const float* __restrict__ n2w1, const float* __restrict__ n2b1,
       const float* __restrict__ n2w2, const float* __restrict__ n2b2,
       const int* __restrict__ batch, float* __restrict__ outX) {
    extern __shared__ float sm[];
    float* sW1  = sm;
    float* sW2  = sm + 26624;
    float* sB1  = sm + 34816;
    float* sB2  = sm + 34944;
    float* sInT = sm + 35008;
    float* sInv = sm + 49152;
    int*   sBat = (int*)(sm + 49216);

    int tid = threadIdx.x, tx = tid & 31, wid = tid >> 5;
    int ty = wid & 7, fh = wid >> 3;
    int fbase = fh*64 + tx*2;
    int f2 = fh*32 + tx;

    for (int i = tid; i < 26624; i += 512) sW1[i] = n2w1[i];
    for (int i = tid; i < 8192;  i += 512) sW2[i] = n2w2[i];
    if (tid < 128) sB1[tid] = n2b1[tid];
    if (tid < 64)  sB2[tid] = n2b2[tid];

    int n0 = blockIdx.x * 64;
    if (tid < 64) {
        int n = n0 + tid;
        if (n < NN) { sBat[tid] = batch[n]; sInv[tid] = 1.f / fmaxf(d_deg[n], 1.f); }
        else        { sBat[tid] = 0;        sInv[tid] = 0.f; }
    }
    __syncthreads();
    for (int idx = tid; idx < 64*64; idx += 512) {
        int node = idx >> 6, k = idx & 63; int n = n0 + node;
        sInT[k*68 + node] = (n < NN) ? x[(size_t)n*64 + k] : 0.f;
    }
    for (int idx = tid; idx < 64*128; idx += 512) {
        int node = idx >> 7, k = idx & 127; int n = n0 + node;
        sInT[(64 + k)*68 + node] = (n < NN) ? d_agg[(size_t)n*128 + PHI32(k)] * sInv[node] : 0.f;
    }
    for (int idx = tid; idx < 64*16; idx += 512) {
        int node = idx >> 4, k = idx & 15;
        sInT[(192 + k)*68 + node] = u[sBat[node]*16 + k];
    }
    __syncthreads();

    ull acc[4][2];
    #pragma unroll
    for (int p = 0; p < 4; p++) {
        acc[p][0] = pack2(sB1[fbase],     sB1[fbase]);
        acc[p][1] = pack2(sB1[fbase + 1], sB1[fbase + 1]);
    }
    #pragma unroll 4
    for (int k = 0; k < 208; k++) {
        float2 B = *(const float2*)&sW1[k*128 + fbase];
        ull bb0 = pack2(B.x, B.x), bb1 = pack2(B.y, B.y);
        float4 A0 = *(const float4*)&sInT[k*68 + ty*8];
        float4 A1 = *(const float4*)&sInT[k*68 + ty*8 + 4];
        ull a0 = pack2(A0.x, A0.y), a1 = pack2(A0.z, A0.w);
        ull a2 = pack2(A1.x, A1.y), a3 = pack2(A1.z, A1.w);
        ffma2(acc[0][0], a0, bb0); ffma2(acc[0][1], a0, bb1);
        ffma2(acc[1][0], a1, bb0); ffma2(acc[1][1], a1, bb1);
        ffma2(acc[2][0], a2, bb0); ffma2(acc[2][1], a2, bb1);
        ffma2(acc[3][0], a3, bb0); ffma2(acc[3][1], a3, bb1);
    }
    __syncthreads();
    #pragma unroll
    for (int p = 0; p < 4; p++) {
        *(ull*)&sInT[(fbase + 0)*68 + ty*8 + 2*p] = relu2(acc[p][0]);
        *(ull*)&sInT[(fbase + 1)*68 + ty*8 + 2*p] = relu2(acc[p][1]);
    }
    __syncthreads();

    ull acc2[4];
    {
        float b = sB2[f2];
        #pragma unroll
        for (int p = 0; p < 4; p++) acc2[p] = pack2(b, b);
    }
    #pragma unroll 4
    for (int k = 0; k < 128; k++) {
        float bs = sW2[k*64 + f2];
        ull bb = pack2(bs, bs);
        float4 A0 = *(const float4*)&sInT[k*68 + ty*8];
        float4 A1 = *(const float4*)&sInT[k*68 + ty*8 + 4];
        ffma2(acc2[0], pack2(A0.x, A0.y), bb);
        ffma2(acc2[1], pack2(A0.z, A0.w), bb);
        ffma2(acc2[2], pack2(A1.x, A1.y), bb);
        ffma2(acc2[3], pack2(A1.z, A1.w), bb);
    }
    #pragma unroll
    for (int p = 0; p < 4; p++) {
        float2 v = unpack2(acc2[p]);
        int node = ty*8 + 2*p;
        int n_lo = n0 + node;
        if (n_lo < NN) {
            outX[(size_t)n_lo*64 + f2] = v.x;
            red_add_f(&d_gsum[sBat[node]*64 + f2], v.x);
        }
        if (n_lo + 1 < NN) {
            outX[(size_t)(n_lo+1)*64 + f2] = v.y;
            red_add_f(&d_gsum[sBat[node+1]*64 + f2], v.y);
        }
    }
}

// ---------------- K4: global MLP ----------------
__global__ void k_glob(const float* __restrict__ u,
                       const float* __restrict__ gw1, const float* __restrict__ gb1,
                       const float* __restrict__ gw2, const float* __restrict__ gb2,
                       float* __restrict__ outU) {
    __shared__ float sin[80];
    __shared__ float sh[128];
    int g = blockIdx.x, tid = threadIdx.x;
    if (tid < 16) sin[tid] = u[g*16 + tid];
    if (tid < 64) {
        float c = fmaxf(d_gcnt[g], 1.f);
        sin[16 + tid] = d_gsum[g*64 + tid] / c;
    }
    __syncthreads();
    float acc = gb1[tid];
    #pragma unroll 8
    for (int k = 0; k < 80; k++) acc += sin[k] * gw1[k*128 + tid];
    sh[tid] = fmaxf(acc, 0.f);
    __syncthreads();
    if (tid < 32) {
        float a2 = gb2[tid];
        #pragma unroll 8
        for (int k = 0; k < 128; k++) a2 += sh[k] * gw2[k*32 + tid];
        outU[g*32 + tid] = a2;
    }
}

// ---------------- launch ----------------
extern "C" void kernel_launch(void* const* d_in, const int* in_sizes, int n_in,
                              void* d_out, int out_size) {
    const float* x     = (const float*)d_in[0];
    const float* ea    = (const float*)d_in[1];
    const float* u     = (const float*)d_in[2];
    const float* ew1   = (const float*)d_in[3];
    const float* eb1   = (const float*)d_in[4];
    const float* ew2   = (const float*)d_in[5];
    const float* eb2   = (const float*)d_in[6];
    const float* n1w1  = (const float*)d_in[7];
    const float* n1b1  = (const float*)d_in[8];
    const float* n1w2  = (const float*)d_in[9];
    const float* n1b2  = (const float*)d_in[10];
    const float* n2w1  = (const float*)d_in[11];
    const float* n2b1  = (const float*)d_in[12];
    const float* n2w2  = (const float*)d_in[13];
    const float* n2b2  = (const float*)d_in[14];
    const float* gw1   = (const float*)d_in[15];
    const float* gb1   = (const float*)d_in[16];
    const float* gw2   = (const float*)d_in[17];
    const float* gb2   = (const float*)d_in[18];
    const int*   ei    = (const int*)d_in[19];
    const int*   batch = (const int*)d_in[20];

    float* out  = (float*)d_out;
    float* outX = out;
    float* outE = out + (size_t)NN*64;
    float* outU = out + (size_t)NN*64 + (size_t)NE*64;

    cudaFuncSetAttribute(k_pre,  cudaFuncAttributeMaxDynamicSharedMemorySize, PRE_SMEM);
    cudaFuncSetAttribute(k2a,    cudaFuncAttributeMaxDynamicSharedMemorySize, S2A_SMEM);
    cudaFuncSetAttribute(k2b,    cudaFuncAttributeMaxDynamicSharedMemorySize, S2B_SMEM);
    cudaFuncSetAttribute(k_node, cudaFuncAttributeMaxDynamicSharedMemorySize, NODE_SMEM);

    k_zero<<<256, 256>>>();
    k_rg<<<(NG*128 + 255)/256, 256>>>(u, ew1);
    k_pre<<<(NN + 63)/64, 512, PRE_SMEM>>>(x, ew1, eb1, n1w1, n1b1, batch);
    k2a<<<PGRID, 1024, S2A_SMEM>>>(ea, ew1, ew2, eb2, ei, outE);
    k2b<<<PGRID, 1024, S2B_SMEM>>>(n1w1, n1w2, n1b2, ei, outE);
    k_count<<<(NE + 255)/256, 256>>>(ei, batch);
    k_node<<<(NN + 63)/64, 512, NODE_SMEM>>>(x, u, n2w1, n2b1, n2w2, n2b2, batch, outX);
    k_glob<<<NG, 128>>>(u, gw1, gb1, gw2, gb2, outU);
}

// round 11
// speedup vs baseline: 1.4813x; 1.2941x over previous
#include <cuda_runtime.h>
#include <cstdint>

#define NN 50000
#define NE 800000
#define NG 256
#define NTILE 6250          // NE / 128
#define PGRID 152

typedef unsigned long long ull;

// TAU16: within 16-blocks, col (8a+2t+b) -> pos (4t+2a+b). Maps fp16-fragment
// column pairs so per-thread seed/scatter quads are contiguous.
__host__ __device__ __forceinline__ int TAU16(int c) {
    int j = c & 15;
    return (c & ~15) | (((j >> 1) & 3) << 2) | (((j >> 3) & 1) << 1) | (j & 1);
}

// ---------------- fp16 mma.sync helpers ----------------
__device__ __forceinline__ uint32_t f2h2(float lo, float hi) {
    uint32_t r; asm("cvt.rn.f16x2.f32 %0, %1, %2;" : "=r"(r) : "f"(hi), "f"(lo)); return r;
}
__device__ __forceinline__ void mma16(float* d, const uint32_t* a, uint32_t b0, uint32_t b1) {
    asm volatile("mma.sync.aligned.m16n8k16.row.col.f32.f16.f16.f32 "
        "{%0,%1,%2,%3},{%4,%5,%6,%7},{%8,%9},{%0,%1,%2,%3};"
        : "+f"(d[0]), "+f"(d[1]), "+f"(d[2]), "+f"(d[3])
        : "r"(a[0]), "r"(a[1]), "r"(a[2]), "r"(a[3]), "r"(b0), "r"(b1));
}

// ---------------- f32x2 helpers ----------------
__device__ __forceinline__ void ffma2(ull &d, ull a, ull b) {
    asm("fma.rn.f32x2 %0, %1, %2, %0;" : "+l"(d) : "l"(a), "l"(b));
}
__device__ __forceinline__ ull pack2(float lo, float hi) {
    ull r; asm("mov.b64 %0, {%1, %2};" : "=l"(r) : "f"(lo), "f"(hi)); return r;
}
__device__ __forceinline__ float2 unpack2(ull v) {
    float2 r; asm("mov.b64 {%0, %1}, %2;" : "=f"(r.x), "=f"(r.y) : "l"(v)); return r;
}
__device__ __forceinline__ ull relu2(ull v) {
    float2 t = unpack2(v);
    return pack2(fmaxf(t.x, 0.f), fmaxf(t.y, 0.f));
}
__device__ __forceinline__ void red_add_v4f(float* p, float a, float b, float c, float d) {
    asm volatile("red.global.add.v4.f32 [%0], {%1,%2,%3,%4};" :: "l"(p), "f"(a), "f"(b), "f"(c), "f"(d) : "memory");
}
__device__ __forceinline__ void red_add_f(float* p, float a) {
    asm volatile("red.global.add.f32 [%0], %1;" :: "l"(p), "f"(a) : "memory");
}

// ---------------- device scratch ----------------
__device__ float d_P [NN*128];   // (x@e_w1[:64] + Rg[batch] + eb1), TAU16 layout
__device__ float d_Q [NN*128];   // TAU16 layout
__device__ float d_Ms[NN*128];   // TAU16 layout
__device__ float d_Rg[NG*128];   // natural layout
__device__ float d_agg[NN*128];  // TAU16 layout
__device__ float d_deg[NN];
__device__ float d_gsum[NG*64];
__device__ float d_gcnt[NG];

// ---------------- K0 / K0b ----------------
__global__ void k_zero() {
    int i = blockIdx.x * blockDim.x + threadIdx.x;
    int stride = gridDim.x * blockDim.x;
    for (int idx = i; idx < NN*128; idx += stride) d_agg[idx] = 0.f;
    for (int idx = i; idx < NN;     idx += stride) d_deg[idx] = 0.f;
    for (int idx = i; idx < NG*64;  idx += stride) d_gsum[idx] = 0.f;
    for (int idx = i; idx < NG;     idx += stride) d_gcnt[idx] = 0.f;
}
__global__ void k_count(const int* __restrict__ ei, const int* __restrict__ batch) {
    int i = blockIdx.x * blockDim.x + threadIdx.x;
    if (i < NE) atomicAdd(&d_deg[ei[NE + i]], 1.f);
    if (i < NN) atomicAdd(&d_gcnt[batch[i]], 1.f);
}

// ---------------- K1b: R = u @ e_w1[160:176] ----------------
__global__ void k_rg(const float* __restrict__ u, const float* __restrict__ ew1) {
    int i = blockIdx.x * blockDim.x + threadIdx.x;
    if (i < NG*128) {
        int g = i >> 7, j = i & 127;
        float acc = 0.f;
        #pragma unroll
        for (int k = 0; k < 16; k++) acc += u[g*16 + k] * ew1[(160 + k)*128 + j];
        d_Rg[i] = acc;
    }
}

// ---------------- K1: precompute PR, Q, Msrc (fp32-exact; TAU16 store) ----------------
#define PRE_SMEM ((4352 + 3*8192 + 256 + 64) * 4)
__global__ void __launch_bounds__(512, 1)
k_pre(const float* __restrict__ x, const float* __restrict__ ew1,
      const float* __restrict__ eb1, const float* __restrict__ n1w1,
      const float* __restrict__ n1b1, const int* __restrict__ batch) {
    extern __shared__ float sm[];
    float* sXT  = sm;
    float* sWa  = sm + 4352;
    float* sWb  = sWa + 8192;
    float* sWm  = sWb + 8192;
    float* sEb1 = sWm + 8192;
    float* sNb1 = sEb1 + 128;
    int*   sBat = (int*)(sNb1 + 128);
    int tid = threadIdx.x;
    for (int i = tid; i < 8192; i += 512) {
        sWa[i] = ew1[i];
        sWb[i] = ew1[64*128 + i];
        sWm[i] = n1w1[i];
    }
    if (tid < 128) { sEb1[tid] = eb1[tid]; sNb1[tid] = n1b1[tid]; }
    int n0 = blockIdx.x * 64;
    if (tid < 64) {
        int n = n0 + tid;
        sBat[tid] = (n < NN) ? batch[n] : 0;
    }
    for (int idx = tid; idx < 64*64; idx += 512) {
        int node = idx >> 6, k = idx & 63;
        int n = n0 + node;
        sXT[k*68 + node] = (n < NN) ? x[(size_t)n*64 + k] : 0.f;
    }
    __syncthreads();
    int tx = tid & 31, wid = tid >> 5;
    int ty = wid & 7, fh = wid >> 3;
    int fbase = fh*64 + tx*2;
    int fdst = TAU16(fbase);     // pair-preserving store position
    for (int which = 0; which < 3; which++) {
        const float* W = (which == 0) ? sWa : (which == 1) ? sWb : sWm;
        ull acc[4][2];
        #pragma unroll
        for (int p = 0; p < 4; p++)
            #pragma unroll
            for (int j = 0; j < 2; j++) {
                float b = (which == 0) ? sEb1[fbase + j] : (which == 2) ? sNb1[fbase + j] : 0.f;
                acc[p][j] = pack2(b, b);
            }
        #pragma unroll 4
        for (int k = 0; k < 64; k++) {
            float2 B = *(const float2*)&W[k*128 + fbase];
            ull bb0 = pack2(B.x, B.x), bb1 = pack2(B.y, B.y);
            float4 A0 = *(const float4*)&sXT[k*68 + ty*8];
            float4 A1 = *(const float4*)&sXT[k*68 + ty*8 + 4];
            ull a0 = pack2(A0.x, A0.y), a1 = pack2(A0.z, A0.w);
            ull a2 = pack2(A1.x, A1.y), a3 = pack2(A1.z, A1.w);
            ffma2(acc[0][0], a0, bb0); ffma2(acc[0][1], a0, bb1);
            ffma2(acc[1][0], a1, bb0); ffma2(acc[1][1], a1, bb1);
            ffma2(acc[2][0], a2, bb0); ffma2(acc[2][1], a2, bb1);
            ffma2(acc[3][0], a3, bb0); ffma2(acc[3][1], a3, bb1);
        }
        float* dst = (which == 0) ? d_P : (which == 1) ? d_Q : d_Ms;
        #pragma unroll
        for (int p = 0; p < 4; p++) {
            float2 v0 = unpack2(acc[p][0]), v1 = unpack2(acc[p][1]);
            int node = ty*8 + 2*p;
            int n_lo = n0 + node;
            if (which == 0) {   // PR-fuse (Rg natural layout)
                if (n_lo < NN) {
                    const float* rg = &d_Rg[(size_t)sBat[node]*128 + fbase];
                    v0.x += rg[0]; v1.x += rg[1];
                }
                if (n_lo + 1 < NN) {
                    const float* rg = &d_Rg[(size_t)sBat[node+1]*128 + fbase];
                    v0.y += rg[0]; v1.y += rg[1];
                }
            }
            if (n_lo < NN)
                *(float2*)&dst[(size_t)n_lo*128 + fdst] = make_float2(v0.x, v1.x);
            if (n_lo + 1 < NN)
                *(float2*)&dst[(size_t)(n_lo+1)*128 + fdst] = make_float2(v0.y, v1.y);
        }
    }
}

// ================= K2a: EdgeModel via fp16 mma.sync — 1024 thr =================
// word layout: sW1p 2048 | sW2p 4096 | sEA 2560 (128e x 40 halves) |
//              sH1 8704 (128e x 136 halves) | sB2 64 | idx 256   = 17728 words
#define S2A_SMEM (17728 * 4)
__global__ void __launch_bounds__(1024, 1)
k2a(const float* __restrict__ ea, const float* __restrict__ ew1,
    const float* __restrict__ ew2, const float* __restrict__ eb2,
    const int* __restrict__ ei, float* __restrict__ outE) {
    extern __shared__ float sm[];
    uint32_t* sW1p = (uint32_t*)sm;               // [((wn*2+s)*2+pr)*128 + lane*4 + q]
    uint32_t* sW2p = (uint32_t*)(sm + 2048);      // [(wn*8+s)*128 + lane*4 + q]
    uint32_t* sEA  = (uint32_t*)(sm + 6144);      // [e*20 + ...] (40 halves/row)
    uint32_t* sH1  = (uint32_t*)(sm + 8704);      // [e*68 + ...] (136 halves/row)
    float*    sB2  = sm + 17408;                  // 64
    int* sRow = (int*)(sm + 17472);
    int* sCol = sRow + 128;

    int tid = threadIdx.x, lane = tid & 31, w = tid >> 5;
    int wm = w & 7, wn = w >> 3;
    int g = lane >> 2, tig = lane & 3;
    int e1 = wm*16 + g, e2 = e1 + 8;

    // ---- W1c^T fp16 fragment staging (2048 words) ----
    for (int i = tid; i < 2048; i += 1024) {
        int q = i & 3, ln = (i >> 2) & 31, pr = (i >> 7) & 1;
        int s = (i >> 8) & 1, wn_ = (i >> 9) & 3;
        int gg = ln >> 2, tt = ln & 3;
        int nt = pr*2 + (q >> 1), hb = q & 1;
        int n = (wn_*4 + nt)*8 + gg;
        int k0 = s*16 + 2*tt + hb*8;
        sW1p[i] = f2h2(ew1[(128 + k0)*128 + n], ew1[(128 + k0 + 1)*128 + n]);
    }
    // ---- W2^T fp16 fragment staging (4096 words) ----
    for (int i = tid; i < 4096; i += 1024) {
        int q = i & 3, ln = (i >> 2) & 31;
        int s = (i >> 7) & 7, wn_ = (i >> 10) & 3;
        int gg = ln >> 2, tt = ln & 3;
        int nt = q >> 1, hb = q & 1;
        int n = (wn_*2 + nt)*8 + gg;
        int k0 = s*16 + 2*tt + hb*8;
        sW2p[i] = f2h2(ew2[k0*64 + n], ew2[(k0 + 1)*64 + n]);
    }
    if (tid < 64) sB2[tid] = eb2[tid];

    for (int t = blockIdx.x; t < NTILE; t += gridDim.x) {
        __syncthreads();
        int e0 = t * 128;
        if (tid < 128) {
            sRow[tid] = ei[e0 + tid];
            sCol[tid] = ei[NE + e0 + tid];
        }
        if (tid < 512) {   // stage EA [128][32] fp16, 40-half stride
            int e = tid >> 2, ch = tid & 3;
            float4 v0 = *(const float4*)&ea[(size_t)(e0 + e)*32 + ch*8];
            float4 v1 = *(const float4*)&ea[(size_t)(e0 + e)*32 + ch*8 + 4];
            *(uint4*)&sEA[e*20 + ch*4] = make_uint4(
                f2h2(v0.x, v0.y), f2h2(v0.z, v0.w), f2h2(v1.x, v1.y), f2h2(v1.z, v1.w));
        }
        __syncthreads();

        int r1 = sRow[e1], cc1 = sCol[e1];
        int r2 = sRow[e2], cc2 = sCol[e2];

        // ---- GEMM1 seeds: PR[row] + Q[col] (TAU16 space, contiguous float4) ----
        float acc[4][4];
        {
            const float4* P1 = (const float4*)&d_P[(size_t)r1*128 + wn*32 + tig*4];
            const float4* Q1 = (const float4*)&d_Q[(size_t)cc1*128 + wn*32 + tig*4];
            const float4* P2 = (const float4*)&d_P[(size_t)r2*128 + wn*32 + tig*4];
            const float4* Q2 = (const float4*)&d_Q[(size_t)cc2*128 + wn*32 + tig*4];
            float4 a0 = P1[0], b0 = Q1[0], a1 = P1[4], b1 = Q1[4];   // +16 floats = +4 float4
            float4 c0 = P2[0], d0 = Q2[0], c1 = P2[4], d1 = Q2[4];
            // block B=0 (nt 0,1): cols {2tig,2tig+1,8+2tig,8+2tig+1}
            acc[0][0] = a0.x + b0.x; acc[0][1] = a0.y + b0.y;
            acc[1][0] = a0.z + b0.z; acc[1][1] = a0.w + b0.w;
            acc[0][2] = c0.x + d0.x; acc[0][3] = c0.y + d0.y;
            acc[1][2] = c0.z + d0.z; acc[1][3] = c0.w + d0.w;
            // block B=1 (nt 2,3)
            acc[2][0] = a1.x + b1.x; acc[2][1] = a1.y + b1.y;
            acc[3][0] = a1.z + b1.z; acc[3][1] = a1.w + b1.w;
            acc[2][2] = c1.x + d1.x; acc[2][3] = c1.y + d1.y;
            acc[3][2] = c1.z + d1.z; acc[3][3] = c1.w + d1.w;
        }
        // ---- GEMM1: += EA @ W1c  (K=32 → 2 fp16 ks-steps) ----
        #pragma unroll
        for (int s = 0; s < 2; s++) {
            uint32_t a[4];
            a[0] = sEA[e1*20 + s*8 + tig];
            a[1] = sEA[e2*20 + s*8 + tig];
            a[2] = sEA[e1*20 + s*8 + tig + 4];
            a[3] = sEA[e2*20 + s*8 + tig + 4];
            uint4 b01 = *(const uint4*)&sW1p[((wn*2 + s)*2 + 0)*128 + lane*4];
            uint4 b23 = *(const uint4*)&sW1p[((wn*2 + s)*2 + 1)*128 + lane*4];
            mma16(acc[0], a, b01.x, b01.y);
            mma16(acc[1], a, b01.z, b01.w);
            mma16(acc[2], a, b23.x, b23.y);
            mma16(acc[3], a, b23.z, b23.w);
        }
        // ---- H1 store (fp16 pairs, natural col order) ----
        #pragma unroll
        for (int nt = 0; nt < 4; nt++) {
            int cu = wn*16 + nt*4 + tig;   // u32 col index = (wn*32+nt*8+2tig)/2
            sH1[e1*68 + cu] = f2h2(fmaxf(acc[nt][0], 0.f), fmaxf(acc[nt][1], 0.f));
            sH1[e2*68 + cu] = f2h2(fmaxf(acc[nt][2], 0.f), fmaxf(acc[nt][3], 0.f));
        }
        __syncthreads();

        // ---- GEMM2: EN = H1 @ W2 + b2  (K=128 → 8 ks; N=64) ----
        float acc2[2][4];
        #pragma unroll
        for (int nt = 0; nt < 2; nt++) {
            int c = wn*16 + nt*8 + tig*2;
            acc2[nt][0] = sB2[c]; acc2[nt][1] = sB2[c+1];
            acc2[nt][2] = sB2[c]; acc2[nt][3] = sB2[c+1];
        }
        #pragma unroll
        for (int s = 0; s < 8; s++) {
            uint32_t a[4];
            a[0] = sH1[e1*68 + s*8 + tig];
            a[1] = sH1[e2*68 + s*8 + tig];
            a[2] = sH1[e1*68 + s*8 + tig + 4];
            a[3] = sH1[e2*68 + s*8 + tig + 4];
            uint4 b = *(const uint4*)&sW2p[(wn*8 + s)*128 + lane*4];
            mma16(acc2[0], a, b.x, b.y);
            mma16(acc2[1], a, b.z, b.w);
        }
        #pragma unroll
        for (int nt = 0; nt < 2; nt++) {
            int c = wn*16 + nt*8 + tig*2;
            *(float2*)&outE[(size_t)(e0 + e1)*64 + c] = make_float2(acc2[nt][0], acc2[nt][1]);
            *(float2*)&outE[(size_t)(e0 + e2)*64 + c] = make_float2(acc2[nt][2], acc2[nt][3]);
        }
    }
}

// ================= K2b: message MLP via fp16 mma.sync — 1024 thr =================
// words: sW3p 4096 | sW4p 8192 | sEN 4608 (72 halves/row) | sH2 8704 | sB4 128 | idx 256 = 25984
#define S2B_SMEM (25984 * 4)
__global__ void __launch_bounds__(1024, 1)
k2b(const float* __restrict__ n1w1, const float* __restrict__ n1w2,
    const float* __restrict__ n1b2,
    const int* __restrict__ ei, const float* __restrict__ edgeNew) {
    extern __shared__ float sm[];
    uint32_t* sW3p = (uint32_t*)sm;               // [((wn*4+s)*2+pr)*128 + lane*4 + q]
    uint32_t* sW4p = (uint32_t*)(sm + 4096);      // [((wn*8+s)*2+pr)*128 + lane*4 + q]
    uint32_t* sEN  = (uint32_t*)(sm + 12288);     // [e*36 + ...] (72 halves/row)
    uint32_t* sH2  = (uint32_t*)(sm + 16896);     // [e*68 + ...] (136 halves/row)
    float*    sB4  = sm + 25600;                  // 128
    int* sRow = (int*)(sm + 25728);
    int* sCol = sRow + 128;

    int tid = threadIdx.x, lane = tid & 31, w = tid >> 5;
    int wm = w & 7, wn = w >> 3;
    int g = lane >> 2, tig = lane & 3;
    int e1 = wm*16 + g, e2 = e1 + 8;

    // ---- W3^T fp16 staging (4096 words) ----
    for (int i = tid; i < 4096; i += 1024) {
        int q = i & 3, ln = (i >> 2) & 31, pr = (i >> 7) & 1;
        int s = (i >> 8) & 3, wn_ = (i >> 10) & 3;
        int gg = ln >> 2, tt = ln & 3;
        int nt = pr*2 + (q >> 1), hb = q & 1;
        int n = (wn_*4 + nt)*8 + gg;
        int k0 = s*16 + 2*tt + hb*8;
        sW3p[i] = f2h2(n1w1[(64 + k0)*128 + n], n1w1[(64 + k0 + 1)*128 + n]);
    }
    // ---- W4^T fp16 staging (8192 words) ----
    for (int i = tid; i < 8192; i += 1024) {
        int q = i & 3, ln = (i >> 2) & 31, pr = (i >> 7) & 1;
        int s = (i >> 8) & 7, wn_ = (i >> 11) & 3;
        int gg = ln >> 2, tt = ln & 3;
        int nt = pr*2 + (q >> 1), hb = q & 1;
        int n = (wn_*4 + nt)*8 + gg;
        int k0 = s*16 + 2*tt + hb*8;
        sW4p[i] = f2h2(n1w2[k0*128 + n], n1w2[(k0 + 1)*128 + n]);
    }
    if (tid < 128) sB4[tid] = n1b2[tid];

    for (int t = blockIdx.x; t < NTILE; t += gridDim.x) {
        __syncthreads();
        int e0 = t * 128;
        if (tid < 128) {
            sRow[tid] = ei[e0 + tid];
            sCol[tid] = ei[NE + e0 + tid];
        }
        {   // stage EN [128][64] fp16, 72-half stride (1024 writer threads)
            int e = tid >> 3, ch = tid & 7;
            float4 v0 = *(const float4*)&edgeNew[(size_t)(e0 + e)*64 + ch*8];
            float4 v1 = *(const float4*)&edgeNew[(size_t)(e0 + e)*64 + ch*8 + 4];
            *(uint4*)&sEN[e*36 + ch*4] = make_uint4(
                f2h2(v0.x, v0.y), f2h2(v0.z, v0.w), f2h2(v1.x, v1.y), f2h2(v1.z, v1.w));
        }
        __syncthreads();

        int r1 = sRow[e1], r2 = sRow[e2];
        int c1 = sCol[e1], c2 = sCol[e2];

        // ---- GEMM3 seeds: Ms[row] (TAU16 space) ----
        float acc[4][4];
        {
            const float4* M1 = (const float4*)&d_Ms[(size_t)r1*128 + wn*32 + tig*4];
            const float4* M2 = (const float4*)&d_Ms[(size_t)r2*128 + wn*32 + tig*4];
            float4 a0 = M1[0], a1 = M1[4], b0 = M2[0], b1 = M2[4];
            acc[0][0] = a0.x; acc[0][1] = a0.y; acc[1][0] = a0.z; acc[1][1] = a0.w;
            acc[0][2] = b0.x; acc[0][3] = b0.y; acc[1][2] = b0.z; acc[1][3] = b0.w;
            acc[2][0] = a1.x; acc[2][1] = a1.y; acc[3][0] = a1.z; acc[3][1] = a1.w;
            acc[2][2] = b1.x; acc[2][3] = b1.y; acc[3][2] = b1.z; acc[3][3] = b1.w;
        }
        // ---- GEMM3: += EN @ W3  (K=64 → 4 ks) ----
        #pragma unroll
        for (int s = 0; s < 4; s++) {
            uint32_t a[4];
            a[0] = sEN[e1*36 + s*8 + tig];
            a[1] = sEN[e2*36 + s*8 + tig];
            a[2] = sEN[e1*36 + s*8 + tig + 4];
            a[3] = sEN[e2*36 + s*8 + tig + 4];
            uint4 b01 = *(const uint4*)&sW3p[((wn*4 + s)*2 + 0)*128 + lane*4];
            uint4 b23 = *(const uint4*)&sW3p[((wn*4 + s)*2 + 1)*128 + lane*4];
            mma16(acc[0], a, b01.x, b01.y);
            mma16(acc[1], a, b01.z, b01.w);
            mma16(acc[2], a, b23.x, b23.y);
            mma16(acc[3], a, b23.z, b23.w);
        }
        #pragma unroll
        for (int nt = 0; nt < 4; nt++) {
            int cu = wn*16 + nt*4 + tig;
            sH2[e1*68 + cu] = f2h2(fmaxf(acc[nt][0], 0.f), fmaxf(acc[nt][1], 0.f));
            sH2[e2*68 + cu] = f2h2(fmaxf(acc[nt][2], 0.f), fmaxf(acc[nt][3], 0.f));
        }
        __syncthreads();

        // ---- GEMM4: m = H2 @ W4 + b4  (K=128 → 8 ks) → TAU16 v4 scatter ----
        float acc4[4][4];
        #pragma unroll
        for (int nt = 0; nt < 4; nt++) {
            int c = wn*32 + nt*8 + tig*2;   // natural col
            acc4[nt][0] = sB4[c]; acc4[nt][1] = sB4[c+1];
            acc4[nt][2] = sB4[c]; acc4[nt][3] = sB4[c+1];
        }
        #pragma unroll
        for (int s = 0; s < 8; s++) {
            uint32_t a[4];
            a[0] = sH2[e1*68 + s*8 + tig];
            a[1] = sH2[e2*68 + s*8 + tig];
            a[2] = sH2[e1*68 + s*8 + tig + 4];
            a[3] = sH2[e2*68 + s*8 + tig + 4];
            uint4 b01 = *(const uint4*)&sW4p[((wn*8 + s)*2 + 0)*128 + lane*4];
            uint4 b23 = *(const uint4*)&sW4p[((wn*8 + s)*2 + 1)*128 + lane*4];
            mma16(acc4[0], a, b01.x, b01.y);
            mma16(acc4[1], a, b01.z, b01.w);
            mma16(acc4[2], a, b23.x, b23.y);
            mma16(acc4[3], a, b23.z, b23.w);
        }
        {   // TAU16 scatter: block a' holds nt pair (2a', 2a'+1) at pos 16a' + 4tig
            float* p1 = &d_agg[(size_t)c1*128 + wn*32 + tig*4];
            red_add_v4f(p1,      acc4[0][0], acc4[0][1], acc4[1][0], acc4[1][1]);
            red_add_v4f(p1 + 16, acc4[2][0], acc4[2][1], acc4[3][0], acc4[3][1]);
            float* p2 = &d_agg[(size_t)c2*128 + wn*32 + tig*4];
            red_add_v4f(p2,      acc4[0][2], acc4[0][3], acc4[1][2], acc4[1][3]);
            red_add_v4f(p2 + 16, acc4[2][2], acc4[2][3], acc4[3][2], acc4[3][3]);
        }
    }
}

// ---------------- K3: node MLP2 + pooling (fp32-exact; un-TAUs agg) ----------------
#define NODE_SMEM (49280 * 4)
__global__ void __launch_bounds__(512, 1)
k_node(const float* __restrict__ x, const float* __restrict__ u,
       const float* __restrict__ n2w1, const float* __restrict__ n2b1,
       const float* __restrict__ n2w2, const float* __restrict__ n2b2,
       const int* __restrict__ batch, float* __restrict__ outX) {
    extern __shared__ float sm[];
    float* sW1  = sm;
    float* sW2  = sm + 26624;
    float* sB1  = sm + 34816;
    float* sB2  = sm + 34944;
    float* sInT = sm + 35008;
    float* sInv = sm + 49152;
    int*   sBat = (int*)(sm + 49216);

    int tid = threadIdx.x, tx = tid & 31, wid = tid >> 5;
    int ty = wid & 7, fh = wid >> 3;
    int fbase = fh*64 + tx*2;
    int f2 = fh*32 + tx;

    for (int i = tid; i < 26624; i += 512) sW1[i] = n2w1[i];
    for (int i = tid; i < 8192;  i += 512) sW2[i] = n2w2[i];
    if (tid < 128) sB1[tid] = n2b1[tid];
    if (tid < 64)  sB2[tid] = n2b2[tid];

    int n0 = blockIdx.x * 64;
    if (tid < 64) {
        int n = n0 + tid;
        if (n < NN) { sBat[tid] = batch[n]; sInv[tid] = 1.f / fmaxf(d_deg[n], 1.f); }
        else        { sBat[tid] = 0;        sInv[tid] = 0.f; }
    }
    __syncthreads();
    for (int idx = tid; idx < 64*64; idx += 512) {
        int node = idx >> 6, k = idx & 63; int n = n0 + node;
        sInT[k*68 + node] = (n < NN) ? x[(size_t)n*64 + k] : 0.f;
    }
    for (int idx = tid; idx < 64*128; idx += 512) {
        int node = idx >> 7, k = idx & 127; int n = n0 + node;
        sInT[(64 + k)*68 + node] = (n < NN) ? d_agg[(size_t)n*128 + TAU16(k)] * sInv[node] : 0.f;
    }
    for (int idx = tid; idx < 64*16; idx += 512) {
        int node = idx >> 4, k = idx & 15;
        sInT[(192 + k)*68 + node] = u[sBat[node]*16 + k];
    }
    __syncthreads();

    ull acc[4][2];
    #pragma unroll
    for (int p = 0; p < 4; p++) {
        acc[p][0] = pack2(sB1[fbase],     sB1[fbase]);
        acc[p][1] = pack2(sB1[fbase + 1], sB1[fbase + 1]);
    }
    #pragma unroll 4
    for (int k = 0; k < 208; k++) {
        float2 B = *(const float2*)&sW1[k*128 + fbase];
        ull bb0 = pack2(B.x, B.x), bb1 = pack2(B.y, B.y);
        float4 A0 = *(const float4*)&sInT[k*68 + ty*8];
        float4 A1 = *(const float4*)&sInT[k*68 + ty*8 + 4];
        ull a0 = pack2(A0.x, A0.y), a1 = pack2(A0.z, A0.w);
        ull a2 = pack2(A1.x, A1.y), a3 = pack2(A1.z, A1.w);
        ffma2(acc[0][0], a0, bb0); ffma2(acc[0][1], a0, bb1);
        ffma2(acc[1][0], a1, bb0); ffma2(acc[1][1], a1, bb1);
        ffma2(acc[2][0], a2, bb0); ffma2(acc[2][1], a2, bb1);
        ffma2(acc[3][0], a3, bb0); ffma2(acc[3][1], a3, bb1);
    }
    __syncthreads();
    #pragma unroll
    for (int p = 0; p < 4; p++) {
        *(ull*)&sInT[(fbase + 0)*68 + ty*8 + 2*p] = relu2(acc[p][0]);
        *(ull*)&sInT[(fbase + 1)*68 + ty*8 + 2*p] = relu2(acc[p][1]);
    }
    __syncthreads();

    ull acc2[4];
    {
        float b = sB2[f2];
        #pragma unroll
        for (int p = 0; p < 4; p++) acc2[p] = pack2(b, b);
    }
    #pragma unroll 4
    for (int k = 0; k < 128; k++) {
        float bs = sW2[k*64 + f2];
        ull bb = pack2(bs, bs);
        float4 A0 = *(const float4*)&sInT[k*68 + ty*8];
        float4 A1 = *(const float4*)&sInT[k*68 + ty*8 + 4];
        ffma2(acc2[0], pack2(A0.x, A0.y), bb);
        ffma2(acc2[1], pack2(A0.z, A0.w), bb);
        ffma2(acc2[2], pack2(A1.x, A1.y), bb);
        ffma2(acc2[3], pack2(A1.z, A1.w), bb);
    }
    #pragma unroll
    for (int p = 0; p < 4; p++) {
        float2 v = unpack2(acc2[p]);
        int node = ty*8 + 2*p;
        int n_lo = n0 + node;
        if (n_lo < NN) {
            outX[(size_t)n_lo*64 + f2] = v.x;
            red_add_f(&d_gsum[sBat[node]*64 + f2], v.x);
        }
        if (n_lo + 1 < NN) {
            outX[(size_t)(n_lo+1)*64 + f2] = v.y;
            red_add_f(&d_gsum[sBat[node+1]*64 + f2], v.y);
        }
    }
}

// ---------------- K4: global MLP ----------------
__global__ void k_glob(const float* __restrict__ u,
                       const float* __restrict__ gw1, const float* __restrict__ gb1,
                       const float* __restrict__ gw2, const float* __restrict__ gb2,
                       float* __restrict__ outU) {
    __shared__ float sin[80];
    __shared__ float sh[128];
    int g = blockIdx.x, tid = threadIdx.x;
    if (tid < 16) sin[tid] = u[g*16 + tid];
    if (tid < 64) {
        float c = fmaxf(d_gcnt[g], 1.f);
        sin[16 + tid] = d_gsum[g*64 + tid] / c;
    }
    __syncthreads();
    float acc = gb1[tid];
    #pragma unroll 8
    for (int k = 0; k < 80; k++) acc += sin[k] * gw1[k*128 + tid];
    sh[tid] = fmaxf(acc, 0.f);
    __syncthreads();
    if (tid < 32) {
        float a2 = gb2[tid];
        #pragma unroll 8
        for (int k = 0; k < 128; k++) a2 += sh[k] * gw2[k*32 + tid];
        outU[g*32 + tid] = a2;
    }
}

// ---------------- launch ----------------
extern "C" void kernel_launch(void* const* d_in, const int* in_sizes, int n_in,
                              void* d_out, int out_size) {
    const float* x     = (const float*)d_in[0];
    const float* ea    = (const float*)d_in[1];
    const float* u     = (const float*)d_in[2];
    const float* ew1   = (const float*)d_in[3];
    const float* eb1   = (const float*)d_in[4];
    const float* ew2   = (const float*)d_in[5];
    const float* eb2   = (const float*)d_in[6];
    const float* n1w1  = (const float*)d_in[7];
    const float* n1b1  = (const float*)d_in[8];
    const float* n1w2  = (const float*)d_in[9];
    const float* n1b2  = (const float*)d_in[10];
    const float* n2w1  = (const float*)d_in[11];
    const float* n2b1  = (const float*)d_in[12];
    const float* n2w2  = (const float*)d_in[13];
    const float* n2b2  = (const float*)d_in[14];
    const float* gw1   = (const float*)d_in[15];
    const float* gb1   = (const float*)d_in[16];
    const float* gw2   = (const float*)d_in[17];
    const float* gb2   = (const float*)d_in[18];
    const int*   ei    = (const int*)d_in[19];
    const int*   batch = (const int*)d_in[20];

    float* out  = (float*)d_out;
    float* outX = out;
    float* outE = out + (size_t)NN*64;
    float* outU = out + (size_t)NN*64 + (size_t)NE*64;

    cudaFuncSetAttribute(k_pre,  cudaFuncAttributeMaxDynamicSharedMemorySize, PRE_SMEM);
    cudaFuncSetAttribute(k2a,    cudaFuncAttributeMaxDynamicSharedMemorySize, S2A_SMEM);
    cudaFuncSetAttribute(k2b,    cudaFuncAttributeMaxDynamicSharedMemorySize, S2B_SMEM);
    cudaFuncSetAttribute(k_node, cudaFuncAttributeMaxDynamicSharedMemorySize, NODE_SMEM);

    k_zero<<<256, 256>>>();
    k_rg<<<(NG*128 + 255)/256, 256>>>(u, ew1);
    k_pre<<<(NN + 63)/64, 512, PRE_SMEM>>>(x, ew1, eb1, n1w1, n1b1, batch);
    k2a<<<PGRID, 1024, S2A_SMEM>>>(ea, ew1, ew2, eb2, ei, outE);
    k2b<<<PGRID, 1024, S2B_SMEM>>>(n1w1, n1w2, n1b2, ei, outE);
    k_count<<<(NE + 255)/256, 256>>>(ei, batch);
    k_node<<<(NN + 63)/64, 512, NODE_SMEM>>>(x, u, n2w1, n2b1, n2w2, n2b2, batch, outX);
    k_glob<<<NG, 128>>>(u, gw1, gb1, gw2, gb2, outU);
}

// round 12
// speedup vs baseline: 1.4838x; 1.0017x over previous
#include <cuda_runtime.h>
#include <cstdint>

#define NN 50000
#define NE 800000
#define NG 256
#define NTILE 6250          // NE / 128
#define PGRID 152

typedef unsigned long long ull;

// TAU16: within 16-blocks, col (8a+2t+b) -> pos (4t+2a+b)
__host__ __device__ __forceinline__ int TAU16(int c) {
    int j = c & 15;
    return (c & ~15) | (((j >> 1) & 3) << 2) | (((j >> 3) & 1) << 1) | (j & 1);
}

// ---------------- fp16 mma.sync helpers ----------------
__device__ __forceinline__ uint32_t f2h2(float lo, float hi) {
    uint32_t r; asm("cvt.rn.f16x2.f32 %0, %1, %2;" : "=r"(r) : "f"(hi), "f"(lo)); return r;
}
__device__ __forceinline__ void mma16(float* d, const uint32_t* a, uint32_t b0, uint32_t b1) {
    asm volatile("mma.sync.aligned.m16n8k16.row.col.f32.f16.f16.f32 "
        "{%0,%1,%2,%3},{%4,%5,%6,%7},{%8,%9},{%0,%1,%2,%3};"
        : "+f"(d[0]), "+f"(d[1]), "+f"(d[2]), "+f"(d[3])
        : "r"(a[0]), "r"(a[1]), "r"(a[2]), "r"(a[3]), "r"(b0), "r"(b1));
}

// ---------------- f32x2 helpers ----------------
__device__ __forceinline__ void ffma2(ull &d, ull a, ull b) {
    asm("fma.rn.f32x2 %0, %1, %2, %0;" : "+l"(d) : "l"(a), "l"(b));
}
__device__ __forceinline__ ull pack2(float lo, float hi) {
    ull r; asm("mov.b64 %0, {%1, %2};" : "=l"(r) : "f"(lo), "f"(hi)); return r;
}
__device__ __forceinline__ float2 unpack2(ull v) {
    float2 r; asm("mov.b64 {%0, %1}, %2;" : "=f"(r.x), "=f"(r.y) : "l"(v)); return r;
}
__device__ __forceinline__ ull relu2(ull v) {
    float2 t = unpack2(v);
    return pack2(fmaxf(t.x, 0.f), fmaxf(t.y, 0.f));
}
__device__ __forceinline__ void red_add_v4f(float* p, float a, float b, float c, float d) {
    asm volatile("red.global.add.v4.f32 [%0], {%1,%2,%3,%4};" :: "l"(p), "f"(a), "f"(b), "f"(c), "f"(d) : "memory");
}
__device__ __forceinline__ void red_add_f(float* p, float a) {
    asm volatile("red.global.add.f32 [%0], %1;" :: "l"(p), "f"(a) : "memory");
}

// ---------------- device scratch ----------------
__device__ float d_P [NN*128];   // (x@e_w1[:64] + Rg[batch] + eb1), TAU16 layout
__device__ float d_Q [NN*128];   // TAU16 layout
__device__ float d_Ms[NN*128];   // TAU16 layout
__device__ float d_Rg[NG*128];   // natural layout
__device__ float d_agg[NN*128];  // TAU16 layout
__device__ float d_deg[NN];
__device__ float d_gsum[NG*64];
__device__ float d_gcnt[NG];

// ---------------- K0 / K0b ----------------
__global__ void k_zero() {
    int i = blockIdx.x * blockDim.x + threadIdx.x;
    int stride = gridDim.x * blockDim.x;
    for (int idx = i; idx < NN*128; idx += stride) d_agg[idx] = 0.f;
    for (int idx = i; idx < NN;     idx += stride) d_deg[idx] = 0.f;
    for (int idx = i; idx < NG*64;  idx += stride) d_gsum[idx] = 0.f;
    for (int idx = i; idx < NG;     idx += stride) d_gcnt[idx] = 0.f;
}
__global__ void k_count(const int* __restrict__ ei, const int* __restrict__ batch) {
    int i = blockIdx.x * blockDim.x + threadIdx.x;
    if (i < NE) atomicAdd(&d_deg[ei[NE + i]], 1.f);
    if (i < NN) atomicAdd(&d_gcnt[batch[i]], 1.f);
}

// ---------------- K1b: R = u @ e_w1[160:176] ----------------
__global__ void k_rg(const float* __restrict__ u, const float* __restrict__ ew1) {
    int i = blockIdx.x * blockDim.x + threadIdx.x;
    if (i < NG*128) {
        int g = i >> 7, j = i & 127;
        float acc = 0.f;
        #pragma unroll
        for (int k = 0; k < 16; k++) acc += u[g*16 + k] * ew1[(160 + k)*128 + j];
        d_Rg[i] = acc;
    }
}

// ---------------- K1: precompute PR, Q, Msrc (fp32-exact; TAU16 store) ----------------
#define PRE_SMEM ((4352 + 3*8192 + 256 + 64) * 4)
__global__ void __launch_bounds__(512, 1)
k_pre(const float* __restrict__ x, const float* __restrict__ ew1,
      const float* __restrict__ eb1, const float* __restrict__ n1w1,
      const float* __restrict__ n1b1, const int* __restrict__ batch) {
    extern __shared__ float sm[];
    float* sXT  = sm;
    float* sWa  = sm + 4352;
    float* sWb  = sWa + 8192;
    float* sWm  = sWb + 8192;
    float* sEb1 = sWm + 8192;
    float* sNb1 = sEb1 + 128;
    int*   sBat = (int*)(sNb1 + 128);
    int tid = threadIdx.x;
    for (int i = tid; i < 8192; i += 512) {
        sWa[i] = ew1[i];
        sWb[i] = ew1[64*128 + i];
        sWm[i] = n1w1[i];
    }
    if (tid < 128) { sEb1[tid] = eb1[tid]; sNb1[tid] = n1b1[tid]; }
    int n0 = blockIdx.x * 64;
    if (tid < 64) {
        int n = n0 + tid;
        sBat[tid] = (n < NN) ? batch[n] : 0;
    }
    for (int idx = tid; idx < 64*64; idx += 512) {
        int node = idx >> 6, k = idx & 63;
        int n = n0 + node;
        sXT[k*68 + node] = (n < NN) ? x[(size_t)n*64 + k] : 0.f;
    }
    __syncthreads();
    int tx = tid & 31, wid = tid >> 5;
    int ty = wid & 7, fh = wid >> 3;
    int fbase = fh*64 + tx*2;
    int fdst = TAU16(fbase);
    for (int which = 0; which < 3; which++) {
        const float* W = (which == 0) ? sWa : (which == 1) ? sWb : sWm;
        ull acc[4][2];
        #pragma unroll
        for (int p = 0; p < 4; p++)
            #pragma unroll
            for (int j = 0; j < 2; j++) {
                float b = (which == 0) ? sEb1[fbase + j] : (which == 2) ? sNb1[fbase + j] : 0.f;
                acc[p][j] = pack2(b, b);
            }
        #pragma unroll 4
        for (int k = 0; k < 64; k++) {
            float2 B = *(const float2*)&W[k*128 + fbase];
            ull bb0 = pack2(B.x, B.x), bb1 = pack2(B.y, B.y);
            float4 A0 = *(const float4*)&sXT[k*68 + ty*8];
            float4 A1 = *(const float4*)&sXT[k*68 + ty*8 + 4];
            ull a0 = pack2(A0.x, A0.y), a1 = pack2(A0.z, A0.w);
            ull a2 = pack2(A1.x, A1.y), a3 = pack2(A1.z, A1.w);
            ffma2(acc[0][0], a0, bb0); ffma2(acc[0][1], a0, bb1);
            ffma2(acc[1][0], a1, bb0); ffma2(acc[1][1], a1, bb1);
            ffma2(acc[2][0], a2, bb0); ffma2(acc[2][1], a2, bb1);
            ffma2(acc[3][0], a3, bb0); ffma2(acc[3][1], a3, bb1);
        }
        float* dst = (which == 0) ? d_P : (which == 1) ? d_Q : d_Ms;
        #pragma unroll
        for (int p = 0; p < 4; p++) {
            float2 v0 = unpack2(acc[p][0]), v1 = unpack2(acc[p][1]);
            int node = ty*8 + 2*p;
            int n_lo = n0 + node;
            if (which == 0) {
                if (n_lo < NN) {
                    const float* rg = &d_Rg[(size_t)sBat[node]*128 + fbase];
                    v0.x += rg[0]; v1.x += rg[1];
                }
                if (n_lo + 1 < NN) {
                    const float* rg = &d_Rg[(size_t)sBat[node+1]*128 + fbase];
                    v0.y += rg[0]; v1.y += rg[1];
                }
            }
            if (n_lo < NN)
                *(float2*)&dst[(size_t)n_lo*128 + fdst] = make_float2(v0.x, v1.x);
            if (n_lo + 1 < NN)
                *(float2*)&dst[(size_t)(n_lo+1)*128 + fdst] = make_float2(v0.y, v1.y);
        }
    }
}

// ================= K2: merged edge pipeline (fp16 mma) — persistent, 1024 thr =================
// word layout:
//   sW1p 2048 | sW2p 4096 | sW3p 4096 | sW4p 8192 | sEA 2560 | sEN 4608 |
//   sH 8704 (H1 then H2) | sB2 64 | sB4 128 | idx 256   = 34752 words (139 KB)
#define S2_SMEM (34752 * 4)
__global__ void __launch_bounds__(1024, 1)
k2(const float* __restrict__ ea, const float* __restrict__ ew1,
   const float* __restrict__ ew2, const float* __restrict__ eb2,
   const float* __restrict__ n1w1, const float* __restrict__ n1w2,
   const float* __restrict__ n1b2,
   const int* __restrict__ ei, float* __restrict__ outE) {
    extern __shared__ float sm[];
    uint32_t* sW1p = (uint32_t*)sm;               // 2048
    uint32_t* sW2p = (uint32_t*)(sm + 2048);      // 4096
    uint32_t* sW3p = (uint32_t*)(sm + 6144);      // 4096
    uint32_t* sW4p = (uint32_t*)(sm + 10240);     // 8192
    uint32_t* sEA  = (uint32_t*)(sm + 18432);     // 2560  [e*20]
    uint32_t* sEN  = (uint32_t*)(sm + 20992);     // 4608  [e*36]
    uint32_t* sH   = (uint32_t*)(sm + 25600);     // 8704  [e*68]
    float*    sB2  = sm + 34304;                  // 64
    float*    sB4  = sm + 34368;                  // 128
    int* sRow = (int*)(sm + 34496);
    int* sCol = sRow + 128;

    int tid = threadIdx.x, lane = tid & 31, w = tid >> 5;
    int wm = w & 7, wn = w >> 3;
    int g = lane >> 2, tig = lane & 3;
    int e1 = wm*16 + g, e2 = e1 + 8;

    // ---- W1c^T fp16 staging (2048 words) ----
    for (int i = tid; i < 2048; i += 1024) {
        int q = i & 3, ln = (i >> 2) & 31, pr = (i >> 7) & 1;
        int s = (i >> 8) & 1, wn_ = (i >> 9) & 3;
        int gg = ln >> 2, tt = ln & 3;
        int nt = pr*2 + (q >> 1), hb = q & 1;
        int n = (wn_*4 + nt)*8 + gg;
        int k0 = s*16 + 2*tt + hb*8;
        sW1p[i] = f2h2(ew1[(128 + k0)*128 + n], ew1[(128 + k0 + 1)*128 + n]);
    }
    // ---- W2^T fp16 staging (4096 words) ----
    for (int i = tid; i < 4096; i += 1024) {
        int q = i & 3, ln = (i >> 2) & 31;
        int s = (i >> 7) & 7, wn_ = (i >> 10) & 3;
        int gg = ln >> 2, tt = ln & 3;
        int nt = q >> 1, hb = q & 1;
        int n = (wn_*2 + nt)*8 + gg;
        int k0 = s*16 + 2*tt + hb*8;
        sW2p[i] = f2h2(ew2[k0*64 + n], ew2[(k0 + 1)*64 + n]);
    }
    // ---- W3^T fp16 staging (4096 words) ----
    for (int i = tid; i < 4096; i += 1024) {
        int q = i & 3, ln = (i >> 2) & 31, pr = (i >> 7) & 1;
        int s = (i >> 8) & 3, wn_ = (i >> 10) & 3;
        int gg = ln >> 2, tt = ln & 3;
        int nt = pr*2 + (q >> 1), hb = q & 1;
        int n = (wn_*4 + nt)*8 + gg;
        int k0 = s*16 + 2*tt + hb*8;
        sW3p[i] = f2h2(n1w1[(64 + k0)*128 + n], n1w1[(64 + k0 + 1)*128 + n]);
    }
    // ---- W4^T fp16 staging (8192 words) ----
    for (int i = tid; i < 8192; i += 1024) {
        int q = i & 3, ln = (i >> 2) & 31, pr = (i >> 7) & 1;
        int s = (i >> 8) & 7, wn_ = (i >> 11) & 3;
        int gg = ln >> 2, tt = ln & 3;
        int nt = pr*2 + (q >> 1), hb = q & 1;
        int n = (wn_*4 + nt)*8 + gg;
        int k0 = s*16 + 2*tt + hb*8;
        sW4p[i] = f2h2(n1w2[k0*128 + n], n1w2[(k0 + 1)*128 + n]);
    }
    if (tid < 64)  sB2[tid] = eb2[tid];
    if (tid < 128) sB4[tid] = n1b2[tid];

    for (int t = blockIdx.x; t < NTILE; t += gridDim.x) {
        __syncthreads();     // previous-tile sH/sEN reads done
        int e0 = t * 128;
        if (tid < 128) {
            sRow[tid] = ei[e0 + tid];
            sCol[tid] = ei[NE + e0 + tid];
        }
        if (tid < 512) {     // stage EA [128][32] fp16 (coalesced)
            int e = tid >> 2, ch = tid & 3;
            float4 v0 = *(const float4*)&ea[(size_t)(e0 + e)*32 + ch*8];
            float4 v1 = *(const float4*)&ea[(size_t)(e0 + e)*32 + ch*8 + 4];
            *(uint4*)&sEA[e*20 + ch*4] = make_uint4(
                f2h2(v0.x, v0.y), f2h2(v0.z, v0.w), f2h2(v1.x, v1.y), f2h2(v1.z, v1.w));
        }
        __syncthreads();

        int r1 = sRow[e1], cc1 = sCol[e1];
        int r2 = sRow[e2], cc2 = sCol[e2];

        // ======== GEMM1: H1 = relu(PR[row] + Q[col] + EA @ W1c) ========
        float acc[4][4];
        {
            const float4* P1 = (const float4*)&d_P[(size_t)r1*128 + wn*32 + tig*4];
            const float4* Q1 = (const float4*)&d_Q[(size_t)cc1*128 + wn*32 + tig*4];
            const float4* P2 = (const float4*)&d_P[(size_t)r2*128 + wn*32 + tig*4];
            const float4* Q2 = (const float4*)&d_Q[(size_t)cc2*128 + wn*32 + tig*4];
            float4 a0 = P1[0], b0 = Q1[0], a1 = P1[4], b1 = Q1[4];
            float4 c0 = P2[0], d0 = Q2[0], c1 = P2[4], d1 = Q2[4];
            acc[0][0] = a0.x + b0.x; acc[0][1] = a0.y + b0.y;
            acc[1][0] = a0.z + b0.z; acc[1][1] = a0.w + b0.w;
            acc[0][2] = c0.x + d0.x; acc[0][3] = c0.y + d0.y;
            acc[1][2] = c0.z + d0.z; acc[1][3] = c0.w + d0.w;
            acc[2][0] = a1.x + b1.x; acc[2][1] = a1.y + b1.y;
            acc[3][0] = a1.z + b1.z; acc[3][1] = a1.w + b1.w;
            acc[2][2] = c1.x + d1.x; acc[2][3] = c1.y + d1.y;
            acc[3][2] = c1.z + d1.z; acc[3][3] = c1.w + d1.w;
        }
        #pragma unroll
        for (int s = 0; s < 2; s++) {
            uint32_t a[4];
            a[0] = sEA[e1*20 + s*8 + tig];
            a[1] = sEA[e2*20 + s*8 + tig];
            a[2] = sEA[e1*20 + s*8 + tig + 4];
            a[3] = sEA[e2*20 + s*8 + tig + 4];
            uint4 b01 = *(const uint4*)&sW1p[((wn*2 + s)*2 + 0)*128 + lane*4];
            uint4 b23 = *(const uint4*)&sW1p[((wn*2 + s)*2 + 1)*128 + lane*4];
            mma16(acc[0], a, b01.x, b01.y);
            mma16(acc[1], a, b01.z, b01.w);
            mma16(acc[2], a, b23.x, b23.y);
            mma16(acc[3], a, b23.z, b23.w);
        }
        #pragma unroll
        for (int nt = 0; nt < 4; nt++) {
            int cu = wn*16 + nt*4 + tig;
            sH[e1*68 + cu] = f2h2(fmaxf(acc[nt][0], 0.f), fmaxf(acc[nt][1], 0.f));
            sH[e2*68 + cu] = f2h2(fmaxf(acc[nt][2], 0.f), fmaxf(acc[nt][3], 0.f));
        }
        __syncthreads();

        // ======== GEMM2: EN = H1 @ W2 + b2  → outE + sEN (fp16, no round-trip) ========
        float acc2[2][4];
        #pragma unroll
        for (int nt = 0; nt < 2; nt++) {
            int c = wn*16 + nt*8 + tig*2;
            acc2[nt][0] = sB2[c]; acc2[nt][1] = sB2[c+1];
            acc2[nt][2] = sB2[c]; acc2[nt][3] = sB2[c+1];
        }
        #pragma unroll
        for (int s = 0; s < 8; s++) {
            uint32_t a[4];
            a[0] = sH[e1*68 + s*8 + tig];
            a[1] = sH[e2*68 + s*8 + tig];
            a[2] = sH[e1*68 + s*8 + tig + 4];
            a[3] = sH[e2*68 + s*8 + tig + 4];
            uint4 b = *(const uint4*)&sW2p[(wn*8 + s)*128 + lane*4];
            mma16(acc2[0], a, b.x, b.y);
            mma16(acc2[1], a, b.z, b.w);
        }
        #pragma unroll
        for (int nt = 0; nt < 2; nt++) {
            int c = wn*16 + nt*8 + tig*2;
            *(float2*)&outE[(size_t)(e0 + e1)*64 + c] = make_float2(acc2[nt][0], acc2[nt][1]);
            *(float2*)&outE[(size_t)(e0 + e2)*64 + c] = make_float2(acc2[nt][2], acc2[nt][3]);
            int cu = wn*8 + nt*4 + tig;
            sEN[e1*36 + cu] = f2h2(acc2[nt][0], acc2[nt][1]);
            sEN[e2*36 + cu] = f2h2(acc2[nt][2], acc2[nt][3]);
        }
        __syncthreads();

        // ======== GEMM3: H2 = relu(Ms[row] + EN @ W3) ========
        {
            const float4* M1 = (const float4*)&d_Ms[(size_t)r1*128 + wn*32 + tig*4];
            const float4* M2 = (const float4*)&d_Ms[(size_t)r2*128 + wn*32 + tig*4];
            float4 a0 = M1[0], a1 = M1[4], b0 = M2[0], b1 = M2[4];
            acc[0][0] = a0.x; acc[0][1] = a0.y; acc[1][0] = a0.z; acc[1][1] = a0.w;
            acc[0][2] = b0.x; acc[0][3] = b0.y; acc[1][2] = b0.z; acc[1][3] = b0.w;
            acc[2][0] = a1.x; acc[2][1] = a1.y; acc[3][0] = a1.z; acc[3][1] = a1.w;
            acc[2][2] = b1.x; acc[2][3] = b1.y; acc[3][2] = b1.z; acc[3][3] = b1.w;
        }
        #pragma unroll
        for (int s = 0; s < 4; s++) {
            uint32_t a[4];
            a[0] = sEN[e1*36 + s*8 + tig];
            a[1] = sEN[e2*36 + s*8 + tig];
            a[2] = sEN[e1*36 + s*8 + tig + 4];
            a[3] = sEN[e2*36 + s*8 + tig + 4];
            uint4 b01 = *(const uint4*)&sW3p[((wn*4 + s)*2 + 0)*128 + lane*4];
            uint4 b23 = *(const uint4*)&sW3p[((wn*4 + s)*2 + 1)*128 + lane*4];
            mma16(acc[0], a, b01.x, b01.y);
            mma16(acc[1], a, b01.z, b01.w);
            mma16(acc[2], a, b23.x, b23.y);
            mma16(acc[3], a, b23.z, b23.w);
        }
        __syncthreads();   // all GEMM2 reads of sH done before overwrite (H2)
        #pragma unroll
        for (int nt = 0; nt < 4; nt++) {
            int cu = wn*16 + nt*4 + tig;
            sH[e1*68 + cu] = f2h2(fmaxf(acc[nt][0], 0.f), fmaxf(acc[nt][1], 0.f));
            sH[e2*68 + cu] = f2h2(fmaxf(acc[nt][2], 0.f), fmaxf(acc[nt][3], 0.f));
        }
        __syncthreads();

        // ======== GEMM4: m = H2 @ W4 + b4 → TAU16 v4 scatter ========
        float acc4[4][4];
        #pragma unroll
        for (int nt = 0; nt < 4; nt++) {
            int c = wn*32 + nt*8 + tig*2;
            acc4[nt][0] = sB4[c]; acc4[nt][1] = sB4[c+1];
            acc4[nt][2] = sB4[c]; acc4[nt][3] = sB4[c+1];
        }
        #pragma unroll
        for (int s = 0; s < 8; s++) {
            uint32_t a[4];
            a[0] = sH[e1*68 + s*8 + tig];
            a[1] = sH[e2*68 + s*8 + tig];
            a[2] = sH[e1*68 + s*8 + tig + 4];
            a[3] = sH[e2*68 + s*8 + tig + 4];
            uint4 b01 = *(const uint4*)&sW4p[((wn*8 + s)*2 + 0)*128 + lane*4];
            uint4 b23 = *(const uint4*)&sW4p[((wn*8 + s)*2 + 1)*128 + lane*4];
            mma16(acc4[0], a, b01.x, b01.y);
            mma16(acc4[1], a, b01.z, b01.w);
            mma16(acc4[2], a, b23.x, b23.y);
            mma16(acc4[3], a, b23.z, b23.w);
        }
        {
            float* p1 = &d_agg[(size_t)cc1*128 + wn*32 + tig*4];
            red_add_v4f(p1,      acc4[0][0], acc4[0][1], acc4[1][0], acc4[1][1]);
            red_add_v4f(p1 + 16, acc4[2][0], acc4[2][1], acc4[3][0], acc4[3][1]);
            float* p2 = &d_agg[(size_t)cc2*128 + wn*32 + tig*4];
            red_add_v4f(p2,      acc4[0][2], acc4[0][3], acc4[1][2], acc4[1][3]);
            red_add_v4f(p2 + 16, acc4[2][2], acc4[2][3], acc4[3][2], acc4[3][3]);
        }
    }
}

// ---------------- K3: node MLP2 + pooling (fp32-exact; un-TAUs agg) ----------------
#define NODE_SMEM (49280 * 4)
__global__ void __launch_bounds__(512, 1)
k_node(const float* __restrict__ x, const float* __restrict__ u,
       const float* __restrict__ n2w1, const float* __restrict__ n2b1,
       const float* __restrict__ n2w2, const float* __restrict__ n2b2,
       const int* __restrict__ batch, float* __restrict__ outX) {
    extern __shared__ float sm[];
    float* sW1  = sm;
    float* sW2  = sm + 26624;
    float* sB1  = sm + 34816;
    float* sB2  = sm + 34944;
    float* sInT = sm + 35008;
    float* sInv = sm + 49152;
    int*   sBat = (int*)(sm + 49216);

    int tid = threadIdx.x, tx = tid & 31, wid = tid >> 5;
    int ty = wid & 7, fh = wid >> 3;
    int fbase = fh*64 + tx*2;
    int f2 = fh*32 + tx;

    for (int i = tid; i < 26624; i += 512) sW1[i] = n2w1[i];
    for (int i = tid; i < 8192;  i += 512) sW2[i] = n2w2[i];
    if (tid < 128) sB1[tid] = n2b1[tid];
    if (tid < 64)  sB2[tid] = n2b2[tid];

    int n0 = blockIdx.x * 64;
    if (tid < 64) {
        int n = n0 + tid;
        if (n < NN) { sBat[tid] = batch[n]; sInv[tid] = 1.f / fmaxf(d_deg[n], 1.f); }
        else        { sBat[tid] = 0;        sInv[tid] = 0.f; }
    }
    __syncthreads();
    for (int idx = tid; idx < 64*64; idx += 512) {
        int node = idx >> 6, k = idx & 63; int n = n0 + node;
        sInT[k*68 + node] = (n < NN) ? x[(size_t)n*64 + k] : 0.f;
    }
    for (int idx = tid; idx < 64*128; idx += 512) {
        int node = idx >> 7, k = idx & 127; int n = n0 + node;
        sInT[(64 + k)*68 + node] = (n < NN) ? d_agg[(size_t)n*128 + TAU16(k)] * sInv[node] : 0.f;
    }
    for (int idx = tid; idx < 64*16; idx += 512) {
        int node = idx >> 4, k = idx & 15;
        sInT[(192 + k)*68 + node] = u[sBat[node]*16 + k];
    }
    __syncthreads();

    ull acc[4][2];
    #pragma unroll
    for (int p = 0; p < 4; p++) {
        acc[p][0] = pack2(sB1[fbase],     sB1[fbase]);
        acc[p][1] = pack2(sB1[fbase + 1], sB1[fbase + 1]);
    }
    #pragma unroll 4
    for (int k = 0; k < 208; k++) {
        float2 B = *(const float2*)&sW1[k*128 + fbase];
        ull bb0 = pack2(B.x, B.x), bb1 = pack2(B.y, B.y);
        float4 A0 = *(const float4*)&sInT[k*68 + ty*8];
        float4 A1 = *(const float4*)&sInT[k*68 + ty*8 + 4];
        ull a0 = pack2(A0.x, A0.y), a1 = pack2(A0.z, A0.w);
        ull a2 = pack2(A1.x, A1.y), a3 = pack2(A1.z, A1.w);
        ffma2(acc[0][0], a0, bb0); ffma2(acc[0][1], a0, bb1);
        ffma2(acc[1][0], a1, bb0); ffma2(acc[1][1], a1, bb1);
        ffma2(acc[2][0], a2, bb0); ffma2(acc[2][1], a2, bb1);
        ffma2(acc[3][0], a3, bb0); ffma2(acc[3][1], a3, bb1);
    }
    __syncthreads();
    #pragma unroll
    for (int p = 0; p < 4; p++) {
        *(ull*)&sInT[(fbase + 0)*68 + ty*8 + 2*p] = relu2(acc[p][0]);
        *(ull*)&sInT[(fbase + 1)*68 + ty*8 + 2*p] = relu2(acc[p][1]);
    }
    __syncthreads();

    ull acc2[4];
    {
        float b = sB2[f2];
        #pragma unroll
        for (int p = 0; p < 4; p++) acc2[p] = pack2(b, b);
    }
    #pragma unroll 4
    for (int k = 0; k < 128; k++) {
        float bs = sW2[k*64 + f2];
        ull bb = pack2(bs, bs);
        float4 A0 = *(const float4*)&sInT[k*68 + ty*8];
        float4 A1 = *(const float4*)&sInT[k*68 + ty*8 + 4];
        ffma2(acc2[0], pack2(A0.x, A0.y), bb);
        ffma2(acc2[1], pack2(A0.z, A0.w), bb);
        ffma2(acc2[2], pack2(A1.x, A1.y), bb);
        ffma2(acc2[3], pack2(A1.z, A1.w), bb);
    }
    #pragma unroll
    for (int p = 0; p < 4; p++) {
        float2 v = unpack2(acc2[p]);
        int node = ty*8 + 2*p;
        int n_lo = n0 + node;
        if (n_lo < NN) {
            outX[(size_t)n_lo*64 + f2] = v.x;
            red_add_f(&d_gsum[sBat[node]*64 + f2], v.x);
        }
        if (n_lo + 1 < NN) {
            outX[(size_t)(n_lo+1)*64 + f2] = v.y;
            red_add_f(&d_gsum[sBat[node+1]*64 + f2], v.y);
        }
    }
}

// ---------------- K4: global MLP ----------------
__global__ void k_glob(const float* __restrict__ u,
                       const float* __restrict__ gw1, const float* __restrict__ gb1,
                       const float* __restrict__ gw2, const float* __restrict__ gb2,
                       float* __restrict__ outU) {
    __shared__ float sin[80];
    __shared__ float sh[128];
    int g = blockIdx.x, tid = threadIdx.x;
    if (tid < 16) sin[tid] = u[g*16 + tid];
    if (tid < 64) {
        float c = fmaxf(d_gcnt[g], 1.f);
        sin[16 + tid] = d_gsum[g*64 + tid] / c;
    }
    __syncthreads();
    float acc = gb1[tid];
    #pragma unroll 8
    for (int k = 0; k < 80; k++) acc += sin[k] * gw1[k*128 + tid];
    sh[tid] = fmaxf(acc, 0.f);
    __syncthreads();
    if (tid < 32) {
        float a2 = gb2[tid];
        #pragma unroll 8
        for (int k = 0; k < 128; k++) a2 += sh[k] * gw2[k*32 + tid];
        outU[g*32 + tid] = a2;
    }
}

// ---------------- launch ----------------
extern "C" void kernel_launch(void* const* d_in, const int* in_sizes, int n_in,
                              void* d_out, int out_size) {
    const float* x     = (const float*)d_in[0];
    const float* ea    = (const float*)d_in[1];
    const float* u     = (const float*)d_in[2];
    const float* ew1   = (const float*)d_in[3];
    const float* eb1   = (const float*)d_in[4];
    const float* ew2   = (const float*)d_in[5];
    const float* eb2   = (const float*)d_in[6];
    const float* n1w1  = (const float*)d_in[7];
    const float* n1b1  = (const float*)d_in[8];
    const float* n1w2  = (const float*)d_in[9];
    const float* n1b2  = (const float*)d_in[10];
    const float* n2w1  = (const float*)d_in[11];
    const float* n2b1  = (const float*)d_in[12];
    const float* n2w2  = (const float*)d_in[13];
    const float* n2b2  = (const float*)d_in[14];
    const float* gw1   = (const float*)d_in[15];
    const float* gb1   = (const float*)d_in[16];
    const float* gw2   = (const float*)d_in[17];
    const float* gb2   = (const float*)d_in[18];
    const int*   ei    = (const int*)d_in[19];
    const int*   batch = (const int*)d_in[20];

    float* out  = (float*)d_out;
    float* outX = out;
    float* outE = out + (size_t)NN*64;
    float* outU = out + (size_t)NN*64 + (size_t)NE*64;

    cudaFuncSetAttribute(k_pre,  cudaFuncAttributeMaxDynamicSharedMemorySize, PRE_SMEM);
    cudaFuncSetAttribute(k2,     cudaFuncAttributeMaxDynamicSharedMemorySize, S2_SMEM);
    cudaFuncSetAttribute(k_node, cudaFuncAttributeMaxDynamicSharedMemorySize, NODE_SMEM);

    k_zero<<<256, 256>>>();
    k_rg<<<(NG*128 + 255)/256, 256>>>(u, ew1);
    k_pre<<<(NN + 63)/64, 512, PRE_SMEM>>>(x, ew1, eb1, n1w1, n1b1, batch);
    k2<<<PGRID, 1024, S2_SMEM>>>(ea, ew1, ew2, eb2, n1w1, n1w2, n1b2, ei, outE);
    k_count<<<(NE + 255)/256, 256>>>(ei, batch);
    k_node<<<(NN + 63)/64, 512, NODE_SMEM>>>(x, u, n2w1, n2b1, n2w2, n2b2, batch, outX);
    k_glob<<<NG, 128>>>(u, gw1, gb1, gw2, gb2, outU);
}